// round 4
// baseline (speedup 1.0000x reference)
#include <cuda_runtime.h>
#include <math.h>

// ----------------------------------------------------------------------------
// Fused MLP3D kernel (fp32, SMEM-tiled, packed fma.rn.f32x2 mainloop).
// One block = 64 points, 256 threads.
// Activations in SMEM transposed: buf[k][pt], row stride LDB=68 floats.
// Weights staged in SMEM lane-DUPLICATED: (w_j, w_j, w_{j+1}, w_{j+1}) so a
// single LDS.128 feeds two packed-point FFMA2 operands.
//
// Pipeline per block:
//   embed (63 feats, zero-padded to 64)            -> bufB
//   GEMM0: x  = emb @ W0 + b0          (K=64/63)   -> bufA
//   GEMM1: h  = relu(x @ W1 + b1)      (K=256)     -> bufB
//   parts: relu(x[:,p] @ W1[p,p] + b1[p]) . Wc[p] + bc[p]   (uses bufA)
//   GEMM2: h2 = relu(h @ W2 + b2)      (K=256)     -> bufA
//   occ:   h2 @ Wocc + bocc
//
// Output: d_out[0..n) = occ ; d_out[n..5n) = part_class [N,4] row-major.
// ----------------------------------------------------------------------------

#define THREADS 256
#define TP      64
#define LDB     68
#define KC      32

typedef unsigned long long ull;

// shared-memory float offsets
#define OFF_A   0
#define OFF_B   (256 * LDB)               // 17408
#define OFF_W   (2 * 256 * LDB)           // 34816 (Wt2: KC*512 = 16384 floats)
#define OFF_RED (OFF_W + KC * 512)        // 51200
#define OFF_WC  (OFF_RED + 256)           // 51456
#define SMEM_FLOATS (OFF_WC + 64)         // 51520 floats = 206080 bytes

__device__ __forceinline__ ull fma2(ull a, ull b, ull c) {
    ull d;
    asm("fma.rn.f32x2 %0, %1, %2, %3;" : "=l"(d) : "l"(a), "l"(b), "l"(c));
    return d;
}

// out[i][j] = act(bias[j] + sum_k inT[k][i] * Wg[k][j]); result stored
// transposed to outT[j][i]. Wg row-major [Kact][256]; K padded loop bound,
// inT rows in [Kact, K) must be zero.
__device__ __forceinline__ void gemm_tile(
    const float* __restrict__ Wg, const float* __restrict__ bias,
    const float* inT, float* outT, float* Wt2,
    int K, int Kact, bool doRelu)
{
    const int t    = threadIdx.x;
    const int lane = t & 31;        // neuron base j = 2*lane + 64*rr + d
    const int i0   = (t >> 5) * 8;  // point group (warp-uniform)

    ull acc[4][2][4];               // [rr][d][point-pair], each = 2 fp32
#pragma unroll
    for (int rr = 0; rr < 4; ++rr)
#pragma unroll
        for (int d = 0; d < 2; ++d)
#pragma unroll
            for (int pp = 0; pp < 4; ++pp) acc[rr][d][pp] = 0ULL;

    for (int k0 = 0; k0 < K; k0 += KC) {
        __syncthreads();
        // stage Wt2[KC][512] duplicated: Wt2[row][2j]=Wt2[row][2j+1]=W[k0+row][j]
#pragma unroll
        for (int r = 0; r < 8; ++r) {
            int idx4 = t + r * 256;            // 0..2047
            int row  = idx4 >> 6;              // 32 rows, 64 float4-src per row
            int col  = (idx4 & 63) << 2;       // source col (j)
            float4 v = make_float4(0.f, 0.f, 0.f, 0.f);
            int gk = k0 + row;
            if (gk < Kact) v = *(const float4*)(Wg + gk * 256 + col);
            float* dst = Wt2 + row * 512 + 2 * col;
            *(float4*)(dst)     = make_float4(v.x, v.x, v.y, v.y);
            *(float4*)(dst + 4) = make_float4(v.z, v.z, v.w, v.w);
        }
        __syncthreads();

#pragma unroll 4
        for (int kk = 0; kk < KC; ++kk) {
            const float* xr = inT + (k0 + kk) * LDB + i0;  // warp-broadcast
            ulonglong2 xa = *(const ulonglong2*)xr;        // pairs (i0,i0+1),(i0+2,i0+3)
            ulonglong2 xb = *(const ulonglong2*)(xr + 4);
            ull xp[4] = {xa.x, xa.y, xb.x, xb.y};
            const float* wrow = Wt2 + kk * 512 + 4 * lane;
#pragma unroll
            for (int rr = 0; rr < 4; ++rr) {
                ulonglong2 wv = *(const ulonglong2*)(wrow + 128 * rr);
#pragma unroll
                for (int pp = 0; pp < 4; ++pp) {
                    acc[rr][0][pp] = fma2(wv.x, xp[pp], acc[rr][0][pp]);
                    acc[rr][1][pp] = fma2(wv.y, xp[pp], acc[rr][1][pp]);
                }
            }
        }
    }

    // bias + activation + transposed store
#pragma unroll
    for (int rr = 0; rr < 4; ++rr)
#pragma unroll
        for (int d = 0; d < 2; ++d) {
            int j = 2 * lane + 64 * rr + d;
            float b = bias[j];
#pragma unroll
            for (int pp = 0; pp < 4; ++pp) {
                float2 v = *(float2*)&acc[rr][d][pp];
                float v0 = v.x + b, v1 = v.y + b;
                if (doRelu) { v0 = fmaxf(v0, 0.f); v1 = fmaxf(v1, 0.f); }
                outT[j * LDB + i0 + 2 * pp]     = v0;
                outT[j * LDB + i0 + 2 * pp + 1] = v1;
            }
        }
    __syncthreads();
}

extern "C" __global__ void __launch_bounds__(THREADS, 1)
mlp3d_kernel(const float* __restrict__ coords,
             const float* __restrict__ W0, const float* __restrict__ b0,
             const float* __restrict__ W1, const float* __restrict__ b1,
             const float* __restrict__ W2, const float* __restrict__ b2,
             const float* __restrict__ Wocc, const float* __restrict__ bocc,
             const float* __restrict__ Wc, const float* __restrict__ bc,
             float* __restrict__ out, int n)
{
    extern __shared__ float sm[];
    float* bufA = sm + OFF_A;
    float* bufB = sm + OFF_B;
    float* Wt   = sm + OFF_W;     // also reused (scalar layout) by parts/occ
    float* sRed = sm + OFF_RED;
    float* sWc  = sm + OFF_WC;

    const int t   = threadIdx.x;
    const int pt0 = blockIdx.x * TP;

    // ---- embedding -> bufB rows 0..62, row 63 zeroed ----
    if (t < TP) bufB[63 * LDB + t] = 0.f;
    if (t < TP * 3) {
        int pt = t / 3, d = t % 3;
        float c = 0.f;
        if (pt0 + pt < n) c = coords[(pt0 + pt) * 3 + d];
        bufB[d * LDB + pt] = c;
        float ang = c;
#pragma unroll
        for (int f = 0; f < 10; ++f) {
            float s, co;
            sincosf(ang, &s, &co);
            bufB[(3 + 6 * f + d) * LDB + pt]     = s;
            bufB[(3 + 6 * f + 3 + d) * LDB + pt] = co;
            ang += ang;
        }
    }
    __syncthreads();

    gemm_tile(W0, b0, bufB, bufA, Wt, 64, 63, false);    // x  -> bufA
    gemm_tile(W1, b1, bufA, bufB, Wt, 256, 256, true);   // h  -> bufB

    // ---- part branches (need x in bufA) ----
    {
        const int pt = t & 63;
        const int q  = t >> 6;          // warp-uniform j-quarter
        for (int p = 0; p < 4; ++p) {
            const int P = p * 64;
            // stage W1[P:P+64, P:P+64] into Wt (row stride 64 floats)
#pragma unroll
            for (int r = 0; r < 4; ++r) {
                int idx4 = t + r * 256;          // 0..1023
                int row  = idx4 >> 4;            // 16 float4 per row
                int col  = (idx4 & 15) << 2;
                *(float4*)(Wt + row * 64 + col) =
                    *(const float4*)(W1 + (P + row) * 256 + P + col);
            }
            if (t < 64) sWc[t] = Wc[p * 256 + P + t];
            __syncthreads();

            float acc[16];
#pragma unroll
            for (int jj = 0; jj < 16; ++jj) acc[jj] = b1[P + q * 16 + jj];
#pragma unroll
            for (int kc = 0; kc < 4; ++kc) {
                float xk[16];
#pragma unroll
                for (int k = 0; k < 16; ++k)
                    xk[k] = bufA[(P + kc * 16 + k) * LDB + pt];
#pragma unroll
                for (int jj = 0; jj < 16; ++jj)
#pragma unroll
                    for (int k = 0; k < 16; ++k)
                        acc[jj] = fmaf(xk[k],
                                       Wt[(kc * 16 + k) * 64 + q * 16 + jj],
                                       acc[jj]);
            }
            float s = 0.f;
#pragma unroll
            for (int jj = 0; jj < 16; ++jj)
                s = fmaf(fmaxf(acc[jj], 0.f), sWc[q * 16 + jj], s);
            sRed[q * 64 + pt] = s;
            __syncthreads();
            if (t < 64 && pt0 + t < n) {
                float cls = bc[p] + sRed[t] + sRed[64 + t]
                                  + sRed[128 + t] + sRed[192 + t];
                out[n + (pt0 + t) * 4 + p] = cls;
            }
            __syncthreads();
        }
    }

    gemm_tile(W2, b2, bufB, bufA, Wt, 256, 256, true);   // h2 -> bufA

    // ---- occ head ----
    Wt[t] = Wocc[t];
    __syncthreads();
    {
        const int pt = t & 63;
        const int q  = t >> 6;
        float s = 0.f;
#pragma unroll
        for (int j = 0; j < 64; ++j)
            s = fmaf(bufA[(q * 64 + j) * LDB + pt], Wt[q * 64 + j], s);
        sRed[q * 64 + pt] = s;
        __syncthreads();
        if (t < 64 && pt0 + t < n)
            out[pt0 + t] = bocc[0] + sRed[t] + sRed[64 + t]
                                   + sRed[128 + t] + sRed[192 + t];
    }
}

extern "C" void kernel_launch(void* const* d_in, const int* in_sizes, int n_in,
                              void* d_out, int out_size)
{
    const float* coords = (const float*)d_in[0];
    const float* W0   = (const float*)d_in[1];
    const float* b0   = (const float*)d_in[2];
    const float* W1   = (const float*)d_in[3];
    const float* b1   = (const float*)d_in[4];
    const float* W2   = (const float*)d_in[5];
    const float* b2   = (const float*)d_in[6];
    const float* Wocc = (const float*)d_in[7];
    const float* bocc = (const float*)d_in[8];
    const float* Wc   = (const float*)d_in[9];
    const float* bc   = (const float*)d_in[10];
    float* out = (float*)d_out;

    int n = in_sizes[0] / 3;
    int blocks = (n + TP - 1) / TP;
    size_t smem = SMEM_FLOATS * sizeof(float);
    cudaFuncSetAttribute(mlp3d_kernel,
                         cudaFuncAttributeMaxDynamicSharedMemorySize,
                         (int)smem);
    mlp3d_kernel<<<blocks, THREADS, smem>>>(coords, W0, b0, W1, b1, W2, b2,
                                            Wocc, bocc, Wc, bc, out, n);
}

// round 5
// speedup vs baseline: 1.5016x; 1.5016x over previous
#include <cuda_runtime.h>
#include <cuda_bf16.h>
#include <math.h>

// ============================================================================
// MLP3D via bf16 mma.sync.m16n8k16 with hi/lo split (3 products).
// Block = 128 points, 256 threads (8 warps, one m16 tile each).
// prep_kernel packs weights into B-fragment order: uint4 per (kt,tig,n) =
//   ( pack(Wh[k0],Wh[k0+1]), pack(Wh[k0+8],Wh[k0+9]), same for lo ),
//   k0 = 16*kt + 2*tig.  Chunk = 1024 uint4 (16KB).
// Chunks: L0 [0..4) kt-chunks, L1 [4..20), L2 [20..36), partDiag [36..40).
// Output: out[0..n) = occ ; out[n..5n) = part_class [N,4] row-major.
// ============================================================================

#define LDA 264               // bf16 elems per activation row (128B-friendly)
#define CH_L0 0
#define CH_L1 4
#define CH_L2 20
#define CH_BD 36
#define N_UNITS (40 * 1024)

__device__ uint4 gW[N_UNITS];

#define SW_OFF  (128 * LDA * 4)          // 135168 (sActH + sActL)
#define SC_OFF  (SW_OFF + 16384)         // 151552
#define SMEM_BYTES (SC_OFF + 1285 * 4 + 12)

typedef unsigned u32;

__device__ __forceinline__ u32 pack2(__nv_bfloat16 a, __nv_bfloat16 b) {
    return (u32)__bfloat16_as_ushort(a) | ((u32)__bfloat16_as_ushort(b) << 16);
}

__device__ __forceinline__ void mma16816(float d[4], const u32 a[4],
                                         u32 b0, u32 b1) {
    asm volatile(
        "mma.sync.aligned.m16n8k16.row.col.f32.bf16.bf16.f32 "
        "{%0,%1,%2,%3},{%4,%5,%6,%7},{%8,%9},{%0,%1,%2,%3};"
        : "+f"(d[0]), "+f"(d[1]), "+f"(d[2]), "+f"(d[3])
        : "r"(a[0]), "r"(a[1]), "r"(a[2]), "r"(a[3]), "r"(b0), "r"(b1));
}

__device__ __forceinline__ void ldsm4(u32 r[4], const __nv_bfloat16* p) {
    u32 a = (u32)__cvta_generic_to_shared(p);
    asm volatile("ldmatrix.sync.aligned.m8n8.x4.shared.b16 {%0,%1,%2,%3}, [%4];"
                 : "=r"(r[0]), "=r"(r[1]), "=r"(r[2]), "=r"(r[3]) : "r"(a));
}

// ---------------------------------------------------------------------------
__global__ void prep_kernel(const float* __restrict__ W0,
                            const float* __restrict__ W1,
                            const float* __restrict__ W2) {
    int idx = blockIdx.x * blockDim.x + threadIdx.x;
    if (idx >= N_UNITS) return;
    const float* W; int Kact, kt, tig, nn, rowOff = 0, colOff = 0;
    if (idx < 4096)        { W = W0; Kact = 63;
        kt = idx >> 10; int r = idx & 1023; tig = r >> 8; nn = r & 255; }
    else if (idx < 20480)  { W = W1; Kact = 256; int u = idx - 4096;
        kt = u >> 10; int r = u & 1023; tig = r >> 8; nn = r & 255; }
    else if (idx < 36864)  { W = W2; Kact = 256; int u = idx - 20480;
        kt = u >> 10; int r = u & 1023; tig = r >> 8; nn = r & 255; }
    else {                   W = W1; Kact = 64; int u = idx - 36864;
        int p = u >> 10; int r = u & 1023;
        kt = r >> 8; tig = (r >> 6) & 3; nn = r & 63;
        rowOff = 64 * p; colOff = 64 * p; }
    int k0 = 16 * kt + 2 * tig;
    int ks[4] = {k0, k0 + 1, k0 + 8, k0 + 9};
    __nv_bfloat16 h[4], l[4];
#pragma unroll
    for (int i = 0; i < 4; ++i) {
        float v = (ks[i] < Kact) ? W[(rowOff + ks[i]) * 256 + colOff + nn] : 0.f;
        h[i] = __float2bfloat16_rn(v);
        l[i] = __float2bfloat16_rn(v - __bfloat162float(h[i]));
    }
    gW[idx] = make_uint4(pack2(h[0], h[1]), pack2(h[2], h[3]),
                         pack2(l[0], l[1]), pack2(l[2], l[3]));
}

// ---------------------------------------------------------------------------
// trunk mainloop: acc[32][4] over N=256, KT k-tiles starting at chunkBase.
template <int KT>
__device__ __forceinline__ void trunk_layer(
    float (&acc)[32][4], int chunkBase,
    const __nv_bfloat16* aPH, const __nv_bfloat16* aPL,
    uint4* sW, int t, int tig, int gid)
{
#pragma unroll
    for (int i = 0; i < 32; ++i)
        acc[i][0] = acc[i][1] = acc[i][2] = acc[i][3] = 0.f;

    uint4 p0, p1, p2, p3;
    { const uint4* g = gW + chunkBase * 1024 + t;
      p0 = g[0]; p1 = g[256]; p2 = g[512]; p3 = g[768]; }
#pragma unroll 1
    for (int kt = 0; kt < KT; ++kt) {
        __syncthreads();
        sW[t] = p0; sW[t + 256] = p1; sW[t + 512] = p2; sW[t + 768] = p3;
        if (kt + 1 < KT) {
            const uint4* g = gW + (chunkBase + kt + 1) * 1024 + t;
            p0 = g[0]; p1 = g[256]; p2 = g[512]; p3 = g[768];
        }
        __syncthreads();
        u32 ah[4], al[4];
        ldsm4(ah, aPH + kt * 16);
        ldsm4(al, aPL + kt * 16);
        const uint4* bp = sW + tig * 256 + gid;
#pragma unroll
        for (int nt = 0; nt < 32; ++nt) {
            uint4 b = bp[nt * 8];
            mma16816(acc[nt], ah, b.x, b.y);
            mma16816(acc[nt], al, b.x, b.y);
            mma16816(acc[nt], ah, b.z, b.w);
        }
    }
}

// ---------------------------------------------------------------------------
__global__ void __launch_bounds__(256, 1)
mlp3d_main(const float* __restrict__ coords,
           const float* __restrict__ b0g, const float* __restrict__ b1g,
           const float* __restrict__ b2g, const float* __restrict__ Woccg,
           const float* __restrict__ boccg, const float* __restrict__ Wcg,
           const float* __restrict__ bcg, float* __restrict__ out, int nTot)
{
    extern __shared__ char smem[];
    __nv_bfloat16* sActH = (__nv_bfloat16*)smem;
    __nv_bfloat16* sActL = sActH + 128 * LDA;
    uint4* sW = (uint4*)(smem + SW_OFF);
    float* sC = (float*)(smem + SC_OFF);
    float *sB0 = sC, *sB1 = sC + 256, *sB2 = sC + 512;
    float *sWocc = sC + 768, *sWcS = sC + 1024, *sEx = sC + 1280;

    const int t = threadIdx.x, wid = t >> 5, lane = t & 31;
    const int tig = lane & 3, gid = lane >> 2;
    const int pt0 = blockIdx.x * 128;

    // const staging
    sB0[t] = b0g[t]; sB1[t] = b1g[t]; sB2[t] = b2g[t]; sWocc[t] = Woccg[t];
    { int p = t >> 6, j = t & 63; sWcS[t] = Wcg[p * 256 + p * 64 + j]; }
    if (t < 4) sEx[t] = bcg[t];
    if (t == 4) sEx[4] = boccg[0];

    // ---- embedding (cols 0..62, col 63 zero) ----
    if (t < 128) { sActH[t * LDA + 63] = __float2bfloat16(0.f);
                   sActL[t * LDA + 63] = __float2bfloat16(0.f); }
    for (int idx = t; idx < 384; idx += 256) {
        int pt = idx / 3, d = idx % 3;
        float c = (pt0 + pt < nTot) ? coords[(pt0 + pt) * 3 + d] : 0.f;
        __nv_bfloat16* rh = sActH + pt * LDA;
        __nv_bfloat16* rl = sActL + pt * LDA;
        __nv_bfloat16 h = __float2bfloat16_rn(c);
        rh[d] = h; rl[d] = __float2bfloat16_rn(c - __bfloat162float(h));
        float ang = c;
#pragma unroll
        for (int f = 0; f < 10; ++f) {
            float s, co; sincosf(ang, &s, &co);
            int cs = 3 + 6 * f + d, cc = cs + 3;
            __nv_bfloat16 hs = __float2bfloat16_rn(s);
            rh[cs] = hs; rl[cs] = __float2bfloat16_rn(s - __bfloat162float(hs));
            __nv_bfloat16 hc = __float2bfloat16_rn(co);
            rh[cc] = hc; rl[cc] = __float2bfloat16_rn(co - __bfloat162float(hc));
            ang += ang;
        }
    }
    __syncthreads();

    // A-fragment lane addressing (ldmatrix.x4)
    const int lr = lane & 7, sel = lane >> 3;
    const int arow = wid * 16 + ((sel & 1) << 3) + lr;
    const int acol = (sel >> 1) << 3;
    const __nv_bfloat16* aPH = sActH + arow * LDA + acol;
    const __nv_bfloat16* aPL = sActL + arow * LDA + acol;

    float acc[32][4];

    // ======== L0: x = emb @ W0 + b0 (no relu) ========
    trunk_layer<4>(acc, CH_L0, aPH, aPL, sW, t, tig, gid);
    {
        int row = wid * 16 + gid;
#pragma unroll
        for (int nt = 0; nt < 32; ++nt) {
            int n = nt * 8 + 2 * tig;
            float ba = sB0[n], bb = sB0[n + 1];
            float v0 = acc[nt][0] + ba, v1 = acc[nt][1] + bb;
            float v2 = acc[nt][2] + ba, v3 = acc[nt][3] + bb;
            __nv_bfloat16 h0 = __float2bfloat16_rn(v0), h1 = __float2bfloat16_rn(v1);
            __nv_bfloat16 h2 = __float2bfloat16_rn(v2), h3 = __float2bfloat16_rn(v3);
            *(u32*)(sActH + row * LDA + n) = pack2(h0, h1);
            *(u32*)(sActL + row * LDA + n) =
                pack2(__float2bfloat16_rn(v0 - __bfloat162float(h0)),
                      __float2bfloat16_rn(v1 - __bfloat162float(h1)));
            *(u32*)(sActH + (row + 8) * LDA + n) = pack2(h2, h3);
            *(u32*)(sActL + (row + 8) * LDA + n) =
                pack2(__float2bfloat16_rn(v2 - __bfloat162float(h2)),
                      __float2bfloat16_rn(v3 - __bfloat162float(h3)));
        }
    }

    // ======== part branches: cls[m][p] ========
    {
        uint4 p0, p1, p2, p3;
        { const uint4* g = gW + CH_BD * 1024 + t;
          p0 = g[0]; p1 = g[256]; p2 = g[512]; p3 = g[768]; }
#pragma unroll 1
        for (int p = 0; p < 4; ++p) {
            __syncthreads();
            sW[t] = p0; sW[t + 256] = p1; sW[t + 512] = p2; sW[t + 768] = p3;
            if (p < 3) {
                const uint4* g = gW + (CH_BD + p + 1) * 1024 + t;
                p0 = g[0]; p1 = g[256]; p2 = g[512]; p3 = g[768];
            }
            __syncthreads();
            float pacc[8][4];
#pragma unroll
            for (int i = 0; i < 8; ++i)
                pacc[i][0] = pacc[i][1] = pacc[i][2] = pacc[i][3] = 0.f;
#pragma unroll
            for (int kt = 0; kt < 4; ++kt) {
                u32 ah[4], al[4];
                ldsm4(ah, aPH + p * 64 + kt * 16);
                ldsm4(al, aPL + p * 64 + kt * 16);
                const uint4* bp = sW + (kt * 4 + tig) * 64 + gid;
#pragma unroll
                for (int nt = 0; nt < 8; ++nt) {
                    uint4 b = bp[nt * 8];
                    mma16816(pacc[nt], ah, b.x, b.y);
                    mma16816(pacc[nt], al, b.x, b.y);
                    mma16816(pacc[nt], ah, b.z, b.w);
                }
            }
            float sA = 0.f, sBv = 0.f;
#pragma unroll
            for (int nt = 0; nt < 8; ++nt) {
                int n = nt * 8 + 2 * tig;
                float ba = sB1[64 * p + n], bb = sB1[64 * p + n + 1];
                float wa = sWcS[64 * p + n], wb = sWcS[64 * p + n + 1];
                sA += fmaxf(pacc[nt][0] + ba, 0.f) * wa
                    + fmaxf(pacc[nt][1] + bb, 0.f) * wb;
                sBv += fmaxf(pacc[nt][2] + ba, 0.f) * wa
                     + fmaxf(pacc[nt][3] + bb, 0.f) * wb;
            }
            sA += __shfl_xor_sync(0xffffffffu, sA, 1);
            sA += __shfl_xor_sync(0xffffffffu, sA, 2);
            sBv += __shfl_xor_sync(0xffffffffu, sBv, 1);
            sBv += __shfl_xor_sync(0xffffffffu, sBv, 2);
            if (tig == 0) {
                int m = wid * 16 + gid;
                if (pt0 + m < nTot)
                    out[nTot + (pt0 + m) * 4 + p] = sA + sEx[p];
                if (pt0 + m + 8 < nTot)
                    out[nTot + (pt0 + m + 8) * 4 + p] = sBv + sEx[p];
            }
        }
    }

    // ======== L1: h = relu(x @ W1 + b1), in-place ========
    trunk_layer<16>(acc, CH_L1, aPH, aPL, sW, t, tig, gid);
    {
        int row = wid * 16 + gid;
#pragma unroll
        for (int nt = 0; nt < 32; ++nt) {
            int n = nt * 8 + 2 * tig;
            float ba = sB1[n], bb = sB1[n + 1];
            float v0 = fmaxf(acc[nt][0] + ba, 0.f), v1 = fmaxf(acc[nt][1] + bb, 0.f);
            float v2 = fmaxf(acc[nt][2] + ba, 0.f), v3 = fmaxf(acc[nt][3] + bb, 0.f);
            __nv_bfloat16 h0 = __float2bfloat16_rn(v0), h1 = __float2bfloat16_rn(v1);
            __nv_bfloat16 h2 = __float2bfloat16_rn(v2), h3 = __float2bfloat16_rn(v3);
            *(u32*)(sActH + row * LDA + n) = pack2(h0, h1);
            *(u32*)(sActL + row * LDA + n) =
                pack2(__float2bfloat16_rn(v0 - __bfloat162float(h0)),
                      __float2bfloat16_rn(v1 - __bfloat162float(h1)));
            *(u32*)(sActH + (row + 8) * LDA + n) = pack2(h2, h3);
            *(u32*)(sActL + (row + 8) * LDA + n) =
                pack2(__float2bfloat16_rn(v2 - __bfloat162float(h2)),
                      __float2bfloat16_rn(v3 - __bfloat162float(h3)));
        }
    }

    // ======== L2 + fused occ head ========
    trunk_layer<16>(acc, CH_L2, aPH, aPL, sW, t, tig, gid);
    {
        float oA = 0.f, oB = 0.f;
#pragma unroll
        for (int nt = 0; nt < 32; ++nt) {
            int n = nt * 8 + 2 * tig;
            float ba = sB2[n], bb = sB2[n + 1];
            float wa = sWocc[n], wb = sWocc[n + 1];
            oA += fmaxf(acc[nt][0] + ba, 0.f) * wa
                + fmaxf(acc[nt][1] + bb, 0.f) * wb;
            oB += fmaxf(acc[nt][2] + ba, 0.f) * wa
                + fmaxf(acc[nt][3] + bb, 0.f) * wb;
        }
        oA += __shfl_xor_sync(0xffffffffu, oA, 1);
        oA += __shfl_xor_sync(0xffffffffu, oA, 2);
        oB += __shfl_xor_sync(0xffffffffu, oB, 1);
        oB += __shfl_xor_sync(0xffffffffu, oB, 2);
        if (tig == 0) {
            int m = wid * 16 + gid;
            if (pt0 + m < nTot)     out[pt0 + m] = oA + sEx[4];
            if (pt0 + m + 8 < nTot) out[pt0 + m + 8] = oB + sEx[4];
        }
    }
}

// ---------------------------------------------------------------------------
extern "C" void kernel_launch(void* const* d_in, const int* in_sizes, int n_in,
                              void* d_out, int out_size)
{
    const float* coords = (const float*)d_in[0];
    const float* W0   = (const float*)d_in[1];
    const float* b0   = (const float*)d_in[2];
    const float* W1   = (const float*)d_in[3];
    const float* b1   = (const float*)d_in[4];
    const float* W2   = (const float*)d_in[5];
    const float* b2   = (const float*)d_in[6];
    const float* Wocc = (const float*)d_in[7];
    const float* bocc = (const float*)d_in[8];
    const float* Wc   = (const float*)d_in[9];
    const float* bc   = (const float*)d_in[10];
    float* out = (float*)d_out;

    int n = in_sizes[0] / 3;
    prep_kernel<<<(N_UNITS + 255) / 256, 256>>>(W0, W1, W2);
    cudaFuncSetAttribute(mlp3d_main,
                         cudaFuncAttributeMaxDynamicSharedMemorySize,
                         SMEM_BYTES);
    mlp3d_main<<<(n + 127) / 128, 256, SMEM_BYTES>>>(
        coords, b0, b1, b2, Wocc, bocc, Wc, bc, out, n);
}

// round 6
// speedup vs baseline: 3.0894x; 2.0574x over previous
#include <cuda_runtime.h>
#include <cuda_bf16.h>
#include <math.h>

// ============================================================================
// MLP3D via bf16 mma.sync.m16n8k16, hi/lo split (3 products).
// Block = 128 points, 256 threads = 8 warps tiled 2(M)x4(N):
//   warp (wm, wn) computes rows [wm*64, wm*64+64) x cols [wn*64, wn*64+64).
// Weights pre-packed by prep_kernel into B-fragment order (uint4 =
//   hi.k01, hi.k89, lo.k01, lo.k89), staged per-k-tile into bank-padded SMEM
//   (tig planes offset by +32B so LDS.128 is conflict-free).
// Output: out[0..n) = occ ; out[n..5n) = part_class [N,4] row-major.
// ============================================================================

#define LDA 264
#define CH_L0 0
#define CH_L1 4
#define CH_L2 20
#define CH_BD 36
#define N_UNITS (40 * 1024)

__device__ uint4 gW[N_UNITS];

#define SW_OFF   (128 * LDA * 4)            // 135168 (sActH + sActL)
#define SW_BYTES 16896                      // max(4*4128, 16*1056)
#define SC_OFF   (SW_OFF + SW_BYTES)        // 152064
#define SMEM_BYTES (SC_OFF + 1800 * 4)

typedef unsigned u32;

__device__ __forceinline__ u32 pack2(__nv_bfloat16 a, __nv_bfloat16 b) {
    return (u32)__bfloat16_as_ushort(a) | ((u32)__bfloat16_as_ushort(b) << 16);
}
__device__ __forceinline__ void mma16816(float d[4], const u32 a[4],
                                         u32 b0, u32 b1) {
    asm volatile(
        "mma.sync.aligned.m16n8k16.row.col.f32.bf16.bf16.f32 "
        "{%0,%1,%2,%3},{%4,%5,%6,%7},{%8,%9},{%0,%1,%2,%3};"
        : "+f"(d[0]), "+f"(d[1]), "+f"(d[2]), "+f"(d[3])
        : "r"(a[0]), "r"(a[1]), "r"(a[2]), "r"(a[3]), "r"(b0), "r"(b1));
}
__device__ __forceinline__ void ldsm4(u32 r[4], const __nv_bfloat16* p) {
    u32 a = (u32)__cvta_generic_to_shared(p);
    asm volatile("ldmatrix.sync.aligned.m8n8.x4.shared.b16 {%0,%1,%2,%3}, [%4];"
                 : "=r"(r[0]), "=r"(r[1]), "=r"(r[2]), "=r"(r[3]) : "r"(a));
}
__device__ __forceinline__ void splitStore(__nv_bfloat16* sH, __nv_bfloat16* sL,
                                           int off, float v0, float v1) {
    __nv_bfloat16 h0 = __float2bfloat16_rn(v0), h1 = __float2bfloat16_rn(v1);
    *(u32*)(sH + off) = pack2(h0, h1);
    *(u32*)(sL + off) = pack2(__float2bfloat16_rn(v0 - __bfloat162float(h0)),
                              __float2bfloat16_rn(v1 - __bfloat162float(h1)));
}

// ---------------------------------------------------------------------------
__global__ void prep_kernel(const float* __restrict__ W0,
                            const float* __restrict__ W1,
                            const float* __restrict__ W2) {
    int idx = blockIdx.x * blockDim.x + threadIdx.x;
    if (idx >= N_UNITS) return;
    const float* W; int Kact, kt, tig, nn, rowOff = 0, colOff = 0;
    if (idx < 4096)        { W = W0; Kact = 63;
        kt = idx >> 10; int r = idx & 1023; tig = r >> 8; nn = r & 255; }
    else if (idx < 20480)  { W = W1; Kact = 256; int u = idx - 4096;
        kt = u >> 10; int r = u & 1023; tig = r >> 8; nn = r & 255; }
    else if (idx < 36864)  { W = W2; Kact = 256; int u = idx - 20480;
        kt = u >> 10; int r = u & 1023; tig = r >> 8; nn = r & 255; }
    else {                   W = W1; Kact = 64; int u = idx - 36864;
        int p = u >> 10; int r = u & 1023;
        kt = r >> 8; tig = (r >> 6) & 3; nn = r & 63;
        rowOff = 64 * p; colOff = 64 * p; }
    int k0 = 16 * kt + 2 * tig;
    int ks[4] = {k0, k0 + 1, k0 + 8, k0 + 9};
    __nv_bfloat16 h[4], l[4];
#pragma unroll
    for (int i = 0; i < 4; ++i) {
        float v = (ks[i] < Kact) ? W[(rowOff + ks[i]) * 256 + colOff + nn] : 0.f;
        h[i] = __float2bfloat16_rn(v);
        l[i] = __float2bfloat16_rn(v - __bfloat162float(h[i]));
    }
    gW[idx] = make_uint4(pack2(h[0], h[1]), pack2(h[2], h[3]),
                         pack2(l[0], l[1]), pack2(l[2], l[3]));
}

// ---------------------------------------------------------------------------
// trunk mainloop: warp (wm,wn) accumulates acc[mt=4][nt=8][4] over KT k-tiles.
template <int KT>
__device__ __forceinline__ void trunk_layer(
    float (&acc)[4][8][4], int chunkBase,
    const __nv_bfloat16* aPH, const __nv_bfloat16* aPL,
    char* sWb, int t, int tig, int gid, int wn)
{
#pragma unroll
    for (int mt = 0; mt < 4; ++mt)
#pragma unroll
        for (int nt = 0; nt < 8; ++nt)
            acc[mt][nt][0] = acc[mt][nt][1] = acc[mt][nt][2] = acc[mt][nt][3] = 0.f;

    uint4 p0, p1, p2, p3;
    { const uint4* g = gW + chunkBase * 1024 + t;
      p0 = g[0]; p1 = g[256]; p2 = g[512]; p3 = g[768]; }
#pragma unroll 1
    for (int kt = 0; kt < KT; ++kt) {
        __syncthreads();
        *(uint4*)(sWb + 0 * 4128 + t * 16) = p0;
        *(uint4*)(sWb + 1 * 4128 + t * 16) = p1;
        *(uint4*)(sWb + 2 * 4128 + t * 16) = p2;
        *(uint4*)(sWb + 3 * 4128 + t * 16) = p3;
        if (kt + 1 < KT) {
            const uint4* g = gW + (chunkBase + kt + 1) * 1024 + t;
            p0 = g[0]; p1 = g[256]; p2 = g[512]; p3 = g[768];
        }
        __syncthreads();
        u32 ah[4][4], al[4][4];
#pragma unroll
        for (int mt = 0; mt < 4; ++mt) {
            ldsm4(ah[mt], aPH + mt * 16 * LDA + kt * 16);
            ldsm4(al[mt], aPL + mt * 16 * LDA + kt * 16);
        }
        const char* bbase = sWb + tig * 4128 + (wn * 64 + gid) * 16;
#pragma unroll
        for (int nt = 0; nt < 8; ++nt) {
            uint4 b = *(const uint4*)(bbase + nt * 128);
#pragma unroll
            for (int mt = 0; mt < 4; ++mt) {
                mma16816(acc[mt][nt], ah[mt], b.x, b.y);
                mma16816(acc[mt][nt], al[mt], b.x, b.y);
                mma16816(acc[mt][nt], ah[mt], b.z, b.w);
            }
        }
    }
}

// ---------------------------------------------------------------------------
__global__ void __launch_bounds__(256, 1)
mlp3d_main(const float* __restrict__ coords,
           const float* __restrict__ b0g, const float* __restrict__ b1g,
           const float* __restrict__ b2g, const float* __restrict__ Woccg,
           const float* __restrict__ boccg, const float* __restrict__ Wcg,
           const float* __restrict__ bcg, float* __restrict__ out, int nTot)
{
    extern __shared__ char smem[];
    __nv_bfloat16* sActH = (__nv_bfloat16*)smem;
    __nv_bfloat16* sActL = sActH + 128 * LDA;
    char* sWb = smem + SW_OFF;
    float* sC = (float*)(smem + SC_OFF);
    float *sB0 = sC, *sB1 = sC + 256, *sB2 = sC + 512;
    float *sWocc = sC + 768, *sWcS = sC + 1024, *sEx = sC + 1280;
    float *sRed = sC + 1288;                    // 512 floats

    const int t = threadIdx.x, wid = t >> 5, lane = t & 31;
    const int tig = lane & 3, gid = lane >> 2;
    const int wm = wid & 1, wn = wid >> 1;
    const int pt0 = blockIdx.x * 128;

    sB0[t] = b0g[t]; sB1[t] = b1g[t]; sB2[t] = b2g[t]; sWocc[t] = Woccg[t];
    { int p = t >> 6, j = t & 63; sWcS[t] = Wcg[p * 256 + p * 64 + j]; }
    if (t < 4) sEx[t] = bcg[t];
    if (t == 4) sEx[4] = boccg[0];

    // ---- embedding (cols 0..62, col 63 zero) ----
    if (t < 128) { sActH[t * LDA + 63] = __float2bfloat16(0.f);
                   sActL[t * LDA + 63] = __float2bfloat16(0.f); }
    for (int idx = t; idx < 384; idx += 256) {
        int pt = idx / 3, d = idx % 3;
        float c = (pt0 + pt < nTot) ? coords[(pt0 + pt) * 3 + d] : 0.f;
        __nv_bfloat16* rh = sActH + pt * LDA;
        __nv_bfloat16* rl = sActL + pt * LDA;
        __nv_bfloat16 h = __float2bfloat16_rn(c);
        rh[d] = h; rl[d] = __float2bfloat16_rn(c - __bfloat162float(h));
        float ang = c;
#pragma unroll
        for (int f = 0; f < 10; ++f) {
            float s, co; sincosf(ang, &s, &co);
            int cs = 3 + 6 * f + d, cc = cs + 3;
            __nv_bfloat16 hs = __float2bfloat16_rn(s);
            rh[cs] = hs; rl[cs] = __float2bfloat16_rn(s - __bfloat162float(hs));
            __nv_bfloat16 hc = __float2bfloat16_rn(co);
            rh[cc] = hc; rl[cc] = __float2bfloat16_rn(co - __bfloat162float(hc));
            ang += ang;
        }
    }
    __syncthreads();

    // A-fragment addressing (ldmatrix.x4): trunk (wm map) and parts (wid map)
    const int lr = lane & 7, sel = lane >> 3;
    const int rowc = ((sel & 1) << 3) + lr, acol = (sel >> 1) << 3;
    const __nv_bfloat16* aPH = sActH + (wm * 64 + rowc) * LDA + acol;
    const __nv_bfloat16* aPL = sActL + (wm * 64 + rowc) * LDA + acol;
    const __nv_bfloat16* aPHp = sActH + (wid * 16 + rowc) * LDA + acol;
    const __nv_bfloat16* aPLp = sActL + (wid * 16 + rowc) * LDA + acol;

    float acc[4][8][4];

    // ======== L0: x = emb @ W0 + b0 (no relu) ========
    trunk_layer<4>(acc, CH_L0, aPH, aPL, sWb, t, tig, gid, wn);
#pragma unroll
    for (int mt = 0; mt < 4; ++mt) {
        int row = wm * 64 + mt * 16 + gid;
#pragma unroll
        for (int nt = 0; nt < 8; ++nt) {
            int n = (wn * 8 + nt) * 8 + 2 * tig;
            float ba = sB0[n], bb = sB0[n + 1];
            splitStore(sActH, sActL, row * LDA + n,
                       acc[mt][nt][0] + ba, acc[mt][nt][1] + bb);
            splitStore(sActH, sActL, (row + 8) * LDA + n,
                       acc[mt][nt][2] + ba, acc[mt][nt][3] + bb);
        }
    }

    // ======== part branches ========
    {
        uint4 p0, p1, p2, p3;
        { const uint4* g = gW + CH_BD * 1024 + t;
          p0 = g[0]; p1 = g[256]; p2 = g[512]; p3 = g[768]; }
        const int pl0 = t >> 6, w64 = t & 63;
#pragma unroll 1
        for (int p = 0; p < 4; ++p) {
            __syncthreads();
            *(uint4*)(sWb + (pl0 +  0) * 1056 + w64 * 16) = p0;
            *(uint4*)(sWb + (pl0 +  4) * 1056 + w64 * 16) = p1;
            *(uint4*)(sWb + (pl0 +  8) * 1056 + w64 * 16) = p2;
            *(uint4*)(sWb + (pl0 + 12) * 1056 + w64 * 16) = p3;
            if (p < 3) {
                const uint4* g = gW + (CH_BD + p + 1) * 1024 + t;
                p0 = g[0]; p1 = g[256]; p2 = g[512]; p3 = g[768];
            }
            __syncthreads();
            float pacc[8][4];
#pragma unroll
            for (int i = 0; i < 8; ++i)
                pacc[i][0] = pacc[i][1] = pacc[i][2] = pacc[i][3] = 0.f;
#pragma unroll
            for (int kt = 0; kt < 4; ++kt) {
                u32 ah[4], al[4];
                ldsm4(ah, aPHp + p * 64 + kt * 16);
                ldsm4(al, aPLp + p * 64 + kt * 16);
                const char* bb = sWb + (kt * 4 + tig) * 1056 + gid * 16;
#pragma unroll
                for (int nt = 0; nt < 8; ++nt) {
                    uint4 b = *(const uint4*)(bb + nt * 128);
                    mma16816(pacc[nt], ah, b.x, b.y);
                    mma16816(pacc[nt], al, b.x, b.y);
                    mma16816(pacc[nt], ah, b.z, b.w);
                }
            }
            float sA = 0.f, sBv = 0.f;
#pragma unroll
            for (int nt = 0; nt < 8; ++nt) {
                int n = nt * 8 + 2 * tig;
                float ba = sB1[64 * p + n], bb2 = sB1[64 * p + n + 1];
                float wa = sWcS[64 * p + n], wb = sWcS[64 * p + n + 1];
                sA += fmaxf(pacc[nt][0] + ba, 0.f) * wa
                    + fmaxf(pacc[nt][1] + bb2, 0.f) * wb;
                sBv += fmaxf(pacc[nt][2] + ba, 0.f) * wa
                     + fmaxf(pacc[nt][3] + bb2, 0.f) * wb;
            }
            sA += __shfl_xor_sync(0xffffffffu, sA, 1);
            sA += __shfl_xor_sync(0xffffffffu, sA, 2);
            sBv += __shfl_xor_sync(0xffffffffu, sBv, 1);
            sBv += __shfl_xor_sync(0xffffffffu, sBv, 2);
            if (tig == 0) {
                int m = wid * 16 + gid;
                if (pt0 + m < nTot)
                    out[nTot + (pt0 + m) * 4 + p] = sA + sEx[p];
                if (pt0 + m + 8 < nTot)
                    out[nTot + (pt0 + m + 8) * 4 + p] = sBv + sEx[p];
            }
        }
    }

    // ======== L1: h = relu(x @ W1 + b1), in-place ========
    trunk_layer<16>(acc, CH_L1, aPH, aPL, sWb, t, tig, gid, wn);
#pragma unroll
    for (int mt = 0; mt < 4; ++mt) {
        int row = wm * 64 + mt * 16 + gid;
#pragma unroll
        for (int nt = 0; nt < 8; ++nt) {
            int n = (wn * 8 + nt) * 8 + 2 * tig;
            float ba = sB1[n], bb = sB1[n + 1];
            splitStore(sActH, sActL, row * LDA + n,
                       fmaxf(acc[mt][nt][0] + ba, 0.f),
                       fmaxf(acc[mt][nt][1] + bb, 0.f));
            splitStore(sActH, sActL, (row + 8) * LDA + n,
                       fmaxf(acc[mt][nt][2] + ba, 0.f),
                       fmaxf(acc[mt][nt][3] + bb, 0.f));
        }
    }

    // ======== L2 + fused occ head (cross-warp reduction over wn) ========
    trunk_layer<16>(acc, CH_L2, aPH, aPL, sWb, t, tig, gid, wn);
#pragma unroll
    for (int mt = 0; mt < 4; ++mt) {
        float oA = 0.f, oB = 0.f;
#pragma unroll
        for (int nt = 0; nt < 8; ++nt) {
            int n = (wn * 8 + nt) * 8 + 2 * tig;
            float ba = sB2[n], bb = sB2[n + 1];
            float wa = sWocc[n], wb = sWocc[n + 1];
            oA += fmaxf(acc[mt][nt][0] + ba, 0.f) * wa
                + fmaxf(acc[mt][nt][1] + bb, 0.f) * wb;
            oB += fmaxf(acc[mt][nt][2] + ba, 0.f) * wa
                + fmaxf(acc[mt][nt][3] + bb, 0.f) * wb;
        }
        oA += __shfl_xor_sync(0xffffffffu, oA, 1);
        oA += __shfl_xor_sync(0xffffffffu, oA, 2);
        oB += __shfl_xor_sync(0xffffffffu, oB, 1);
        oB += __shfl_xor_sync(0xffffffffu, oB, 2);
        if (tig == 0) {
            int row = wm * 64 + mt * 16 + gid;
            sRed[wn * 128 + row] = oA;
            sRed[wn * 128 + row + 8] = oB;
        }
    }
    __syncthreads();
    if (t < 128 && pt0 + t < nTot)
        out[pt0 + t] = sEx[4] + sRed[t] + sRed[128 + t]
                               + sRed[256 + t] + sRed[384 + t];
}

// ---------------------------------------------------------------------------
extern "C" void kernel_launch(void* const* d_in, const int* in_sizes, int n_in,
                              void* d_out, int out_size)
{
    const float* coords = (const float*)d_in[0];
    const float* W0 = (const float*)d_in[1];
    const float* W1 = (const float*)d_in[3];
    const float* W2 = (const float*)d_in[5];
    float* out = (float*)d_out;

    int n = in_sizes[0] / 3;
    prep_kernel<<<(N_UNITS + 255) / 256, 256>>>(W0, W1, W2);
    cudaFuncSetAttribute(mlp3d_main,
                         cudaFuncAttributeMaxDynamicSharedMemorySize,
                         SMEM_BYTES);
    mlp3d_main<<<(n + 127) / 128, 256, SMEM_BYTES>>>(
        coords, (const float*)d_in[2], (const float*)d_in[4],
        (const float*)d_in[6], (const float*)d_in[7], (const float*)d_in[8],
        (const float*)d_in[9], (const float*)d_in[10], out, n);
}

// round 7
// speedup vs baseline: 3.3288x; 1.0775x over previous
#include <cuda_runtime.h>
#include <cuda_bf16.h>
#include <math.h>

// ============================================================================
// MLP3D via bf16 mma.sync.m16n8k16, hi/lo split (3 products).
// Block = 128 points, 256 threads = 8 warps tiled 2(M)x4(N).
// B fragments are pre-packed by prep_kernel (uint4 = hi.k01,hi.k89,lo.k01,
// lo.k89) and read DIRECTLY from L2 via LDG.128 with one-k-tile register
// ping-pong prefetch — no SMEM staging, no per-k-tile barriers.
// MMA order interleaves 2 n-tiles x 3 products => dep distance 8.
// Output: out[0..n) = occ ; out[n..5n) = part_class [N,4] row-major.
// ============================================================================

#define LDA 264
#define CH_L0 0
#define CH_L1 4
#define CH_L2 20
#define CH_BD 36
#define N_UNITS (40 * 1024)

__device__ uint4 gW[N_UNITS];

#define SC_OFF (128 * LDA * 4)             // 135168 (sActH + sActL)
#define SMEM_BYTES (SC_OFF + 1800 * 4)

typedef unsigned u32;

__device__ __forceinline__ u32 pack2(__nv_bfloat16 a, __nv_bfloat16 b) {
    return (u32)__bfloat16_as_ushort(a) | ((u32)__bfloat16_as_ushort(b) << 16);
}
__device__ __forceinline__ void mma16816(float d[4], const u32 a[4],
                                         u32 b0, u32 b1) {
    asm volatile(
        "mma.sync.aligned.m16n8k16.row.col.f32.bf16.bf16.f32 "
        "{%0,%1,%2,%3},{%4,%5,%6,%7},{%8,%9},{%0,%1,%2,%3};"
        : "+f"(d[0]), "+f"(d[1]), "+f"(d[2]), "+f"(d[3])
        : "r"(a[0]), "r"(a[1]), "r"(a[2]), "r"(a[3]), "r"(b0), "r"(b1));
}
__device__ __forceinline__ void ldsm4(u32 r[4], const __nv_bfloat16* p) {
    u32 a = (u32)__cvta_generic_to_shared(p);
    asm volatile("ldmatrix.sync.aligned.m8n8.x4.shared.b16 {%0,%1,%2,%3}, [%4];"
                 : "=r"(r[0]), "=r"(r[1]), "=r"(r[2]), "=r"(r[3]) : "r"(a));
}
__device__ __forceinline__ void splitStore(__nv_bfloat16* sH, __nv_bfloat16* sL,
                                           int off, float v0, float v1) {
    __nv_bfloat16 h0 = __float2bfloat16_rn(v0), h1 = __float2bfloat16_rn(v1);
    *(u32*)(sH + off) = pack2(h0, h1);
    *(u32*)(sL + off) = pack2(__float2bfloat16_rn(v0 - __bfloat162float(h0)),
                              __float2bfloat16_rn(v1 - __bfloat162float(h1)));
}

// ---------------------------------------------------------------------------
__global__ void prep_kernel(const float* __restrict__ W0,
                            const float* __restrict__ W1,
                            const float* __restrict__ W2) {
    int idx = blockIdx.x * blockDim.x + threadIdx.x;
    if (idx >= N_UNITS) return;
    const float* W; int Kact, kt, tig, nn, rowOff = 0, colOff = 0;
    if (idx < 4096)        { W = W0; Kact = 63;
        kt = idx >> 10; int r = idx & 1023; tig = r >> 8; nn = r & 255; }
    else if (idx < 20480)  { W = W1; Kact = 256; int u = idx - 4096;
        kt = u >> 10; int r = u & 1023; tig = r >> 8; nn = r & 255; }
    else if (idx < 36864)  { W = W2; Kact = 256; int u = idx - 20480;
        kt = u >> 10; int r = u & 1023; tig = r >> 8; nn = r & 255; }
    else {                   W = W1; Kact = 64; int u = idx - 36864;
        int p = u >> 10; int r = u & 1023;
        kt = r >> 8; tig = (r >> 6) & 3; nn = r & 63;
        rowOff = 64 * p; colOff = 64 * p; }
    int k0 = 16 * kt + 2 * tig;
    int ks[4] = {k0, k0 + 1, k0 + 8, k0 + 9};
    __nv_bfloat16 h[4], l[4];
#pragma unroll
    for (int i = 0; i < 4; ++i) {
        float v = (ks[i] < Kact) ? W[(rowOff + ks[i]) * 256 + colOff + nn] : 0.f;
        h[i] = __float2bfloat16_rn(v);
        l[i] = __float2bfloat16_rn(v - __bfloat162float(h[i]));
    }
    gW[idx] = make_uint4(pack2(h[0], h[1]), pack2(h[2], h[3]),
                         pack2(l[0], l[1]), pack2(l[2], l[3]));
}

// ---------------------------------------------------------------------------
// one k-tile: ldsm A, prefetch next B into bn, 96 MMAs on bc (dep distance 8)
__device__ __forceinline__ void kt_step(
    float (&acc)[4][8][4], const uint4* __restrict__ gB,
    uint4 (&bc)[8], uint4 (&bn)[8], int ktNext, int KT, int kt,
    const __nv_bfloat16* aPH, const __nv_bfloat16* aPL)
{
    u32 ah[4][4], al[4][4];
#pragma unroll
    for (int mt = 0; mt < 4; ++mt) {
        ldsm4(ah[mt], aPH + mt * 16 * LDA + kt * 16);
        ldsm4(al[mt], aPL + mt * 16 * LDA + kt * 16);
    }
    if (ktNext < KT) {
#pragma unroll
        for (int nt = 0; nt < 8; ++nt) bn[nt] = gB[ktNext * 1024 + nt * 8];
    }
#pragma unroll
    for (int np = 0; np < 4; ++np) {
        const int n0 = 2 * np, n1 = n0 + 1;
#pragma unroll
        for (int mt = 0; mt < 4; ++mt) mma16816(acc[mt][n0], ah[mt], bc[n0].x, bc[n0].y);
#pragma unroll
        for (int mt = 0; mt < 4; ++mt) mma16816(acc[mt][n1], ah[mt], bc[n1].x, bc[n1].y);
#pragma unroll
        for (int mt = 0; mt < 4; ++mt) mma16816(acc[mt][n0], al[mt], bc[n0].x, bc[n0].y);
#pragma unroll
        for (int mt = 0; mt < 4; ++mt) mma16816(acc[mt][n1], al[mt], bc[n1].x, bc[n1].y);
#pragma unroll
        for (int mt = 0; mt < 4; ++mt) mma16816(acc[mt][n0], ah[mt], bc[n0].z, bc[n0].w);
#pragma unroll
        for (int mt = 0; mt < 4; ++mt) mma16816(acc[mt][n1], ah[mt], bc[n1].z, bc[n1].w);
    }
}

template <int KT>
__device__ __forceinline__ void trunk_layer(
    float (&acc)[4][8][4], int chunkBase,
    const __nv_bfloat16* aPH, const __nv_bfloat16* aPL,
    int tig, int gid, int wn)
{
#pragma unroll
    for (int mt = 0; mt < 4; ++mt)
#pragma unroll
        for (int nt = 0; nt < 8; ++nt)
            acc[mt][nt][0] = acc[mt][nt][1] = acc[mt][nt][2] = acc[mt][nt][3] = 0.f;

    const uint4* __restrict__ gB = gW + chunkBase * 1024 + tig * 256 + wn * 64 + gid;
    uint4 bc[8], bn[8];
#pragma unroll
    for (int nt = 0; nt < 8; ++nt) bc[nt] = gB[nt * 8];
#pragma unroll 1
    for (int kt = 0; kt < KT; kt += 2) {          // KT is even
        kt_step(acc, gB, bc, bn, kt + 1, KT, kt,     aPH, aPL);
        kt_step(acc, gB, bn, bc, kt + 2, KT, kt + 1, aPH, aPL);
    }
}

// ---------------------------------------------------------------------------
__global__ void __launch_bounds__(256, 1)
mlp3d_main(const float* __restrict__ coords,
           const float* __restrict__ b0g, const float* __restrict__ b1g,
           const float* __restrict__ b2g, const float* __restrict__ Woccg,
           const float* __restrict__ boccg, const float* __restrict__ Wcg,
           const float* __restrict__ bcg, float* __restrict__ out, int nTot)
{
    extern __shared__ char smem[];
    __nv_bfloat16* sActH = (__nv_bfloat16*)smem;
    __nv_bfloat16* sActL = sActH + 128 * LDA;
    float* sC = (float*)(smem + SC_OFF);
    float *sB0 = sC, *sB1 = sC + 256, *sB2 = sC + 512;
    float *sWocc = sC + 768, *sWcS = sC + 1024, *sEx = sC + 1280;
    float *sRed = sC + 1288;                      // 512 floats

    const int t = threadIdx.x, wid = t >> 5, lane = t & 31;
    const int tig = lane & 3, gid = lane >> 2;
    const int wm = wid & 1, wn = wid >> 1;
    const int pt0 = blockIdx.x * 128;

    sB0[t] = b0g[t]; sB1[t] = b1g[t]; sB2[t] = b2g[t]; sWocc[t] = Woccg[t];
    { int p = t >> 6, j = t & 63; sWcS[t] = Wcg[p * 256 + p * 64 + j]; }
    if (t < 4) sEx[t] = bcg[t];
    if (t == 4) sEx[4] = boccg[0];

    // ---- embedding (cols 0..62, col 63 zero) ----
    if (t < 128) { sActH[t * LDA + 63] = __float2bfloat16(0.f);
                   sActL[t * LDA + 63] = __float2bfloat16(0.f); }
    for (int idx = t; idx < 384; idx += 256) {
        int pt = idx / 3, d = idx % 3;
        float c = (pt0 + pt < nTot) ? coords[(pt0 + pt) * 3 + d] : 0.f;
        __nv_bfloat16* rh = sActH + pt * LDA;
        __nv_bfloat16* rl = sActL + pt * LDA;
        __nv_bfloat16 h = __float2bfloat16_rn(c);
        rh[d] = h; rl[d] = __float2bfloat16_rn(c - __bfloat162float(h));
        float ang = c;
#pragma unroll
        for (int f = 0; f < 10; ++f) {
            float s, co; sincosf(ang, &s, &co);
            int cs = 3 + 6 * f + d, cc = cs + 3;
            __nv_bfloat16 hs = __float2bfloat16_rn(s);
            rh[cs] = hs; rl[cs] = __float2bfloat16_rn(s - __bfloat162float(hs));
            __nv_bfloat16 hc = __float2bfloat16_rn(co);
            rh[cc] = hc; rl[cc] = __float2bfloat16_rn(co - __bfloat162float(hc));
            ang += ang;
        }
    }
    __syncthreads();

    const int lr = lane & 7, sel = lane >> 3;
    const int rowc = ((sel & 1) << 3) + lr, acol = (sel >> 1) << 3;
    const __nv_bfloat16* aPH = sActH + (wm * 64 + rowc) * LDA + acol;
    const __nv_bfloat16* aPL = sActL + (wm * 64 + rowc) * LDA + acol;
    const __nv_bfloat16* aPHp = sActH + (wid * 16 + rowc) * LDA + acol;
    const __nv_bfloat16* aPLp = sActL + (wid * 16 + rowc) * LDA + acol;

    float acc[4][8][4];

    // ======== L0: x = emb @ W0 + b0 (no relu) ========
    trunk_layer<4>(acc, CH_L0, aPH, aPL, tig, gid, wn);
    __syncthreads();
#pragma unroll
    for (int mt = 0; mt < 4; ++mt) {
        int row = wm * 64 + mt * 16 + gid;
#pragma unroll
        for (int nt = 0; nt < 8; ++nt) {
            int n = (wn * 8 + nt) * 8 + 2 * tig;
            float ba = sB0[n], bb = sB0[n + 1];
            splitStore(sActH, sActL, row * LDA + n,
                       acc[mt][nt][0] + ba, acc[mt][nt][1] + bb);
            splitStore(sActH, sActL, (row + 8) * LDA + n,
                       acc[mt][nt][2] + ba, acc[mt][nt][3] + bb);
        }
    }
    __syncthreads();

    // ======== part branches (read x; direct-from-global B) ========
#pragma unroll 1
    for (int p = 0; p < 4; ++p) {
        const uint4* __restrict__ gBp =
            gW + (CH_BD + p) * 1024 + tig * 64 + gid;
        float pacc[8][4];
#pragma unroll
        for (int i = 0; i < 8; ++i)
            pacc[i][0] = pacc[i][1] = pacc[i][2] = pacc[i][3] = 0.f;
        uint4 pc[8], pn[8];
#pragma unroll
        for (int nt = 0; nt < 8; ++nt) pc[nt] = gBp[nt * 8];
#pragma unroll
        for (int kt = 0; kt < 4; ++kt) {
            u32 ah[4], al[4];
            ldsm4(ah, aPHp + p * 64 + kt * 16);
            ldsm4(al, aPLp + p * 64 + kt * 16);
            if (kt < 3) {
#pragma unroll
                for (int nt = 0; nt < 8; ++nt)
                    pn[nt] = gBp[(kt + 1) * 256 + nt * 8];
            }
#pragma unroll
            for (int np = 0; np < 4; ++np) {
                const int n0 = 2 * np, n1 = n0 + 1;
                mma16816(pacc[n0], ah, pc[n0].x, pc[n0].y);
                mma16816(pacc[n1], ah, pc[n1].x, pc[n1].y);
                mma16816(pacc[n0], al, pc[n0].x, pc[n0].y);
                mma16816(pacc[n1], al, pc[n1].x, pc[n1].y);
                mma16816(pacc[n0], ah, pc[n0].z, pc[n0].w);
                mma16816(pacc[n1], ah, pc[n1].z, pc[n1].w);
            }
#pragma unroll
            for (int nt = 0; nt < 8; ++nt) pc[nt] = pn[nt];
        }
        float sA = 0.f, sBv = 0.f;
#pragma unroll
        for (int nt = 0; nt < 8; ++nt) {
            int n = nt * 8 + 2 * tig;
            float ba = sB1[64 * p + n], bb2 = sB1[64 * p + n + 1];
            float wa = sWcS[64 * p + n], wb = sWcS[64 * p + n + 1];
            sA += fmaxf(pacc[nt][0] + ba, 0.f) * wa
                + fmaxf(pacc[nt][1] + bb2, 0.f) * wb;
            sBv += fmaxf(pacc[nt][2] + ba, 0.f) * wa
                 + fmaxf(pacc[nt][3] + bb2, 0.f) * wb;
        }
        sA += __shfl_xor_sync(0xffffffffu, sA, 1);
        sA += __shfl_xor_sync(0xffffffffu, sA, 2);
        sBv += __shfl_xor_sync(0xffffffffu, sBv, 1);
        sBv += __shfl_xor_sync(0xffffffffu, sBv, 2);
        if (tig == 0) {
            int m = wid * 16 + gid;
            if (pt0 + m < nTot)
                out[nTot + (pt0 + m) * 4 + p] = sA + sEx[p];
            if (pt0 + m + 8 < nTot)
                out[nTot + (pt0 + m + 8) * 4 + p] = sBv + sEx[p];
        }
    }

    // ======== L1: h = relu(x @ W1 + b1), in-place ========
    trunk_layer<16>(acc, CH_L1, aPH, aPL, tig, gid, wn);
    __syncthreads();
#pragma unroll
    for (int mt = 0; mt < 4; ++mt) {
        int row = wm * 64 + mt * 16 + gid;
#pragma unroll
        for (int nt = 0; nt < 8; ++nt) {
            int n = (wn * 8 + nt) * 8 + 2 * tig;
            float ba = sB1[n], bb = sB1[n + 1];
            splitStore(sActH, sActL, row * LDA + n,
                       fmaxf(acc[mt][nt][0] + ba, 0.f),
                       fmaxf(acc[mt][nt][1] + bb, 0.f));
            splitStore(sActH, sActL, (row + 8) * LDA + n,
                       fmaxf(acc[mt][nt][2] + ba, 0.f),
                       fmaxf(acc[mt][nt][3] + bb, 0.f));
        }
    }
    __syncthreads();

    // ======== L2 + fused occ head (cross-warp reduction over wn) ========
    trunk_layer<16>(acc, CH_L2, aPH, aPL, tig, gid, wn);
#pragma unroll
    for (int mt = 0; mt < 4; ++mt) {
        float oA = 0.f, oB = 0.f;
#pragma unroll
        for (int nt = 0; nt < 8; ++nt) {
            int n = (wn * 8 + nt) * 8 + 2 * tig;
            float ba = sB2[n], bb = sB2[n + 1];
            float wa = sWocc[n], wb = sWocc[n + 1];
            oA += fmaxf(acc[mt][nt][0] + ba, 0.f) * wa
                + fmaxf(acc[mt][nt][1] + bb, 0.f) * wb;
            oB += fmaxf(acc[mt][nt][2] + ba, 0.f) * wa
                + fmaxf(acc[mt][nt][3] + bb, 0.f) * wb;
        }
        oA += __shfl_xor_sync(0xffffffffu, oA, 1);
        oA += __shfl_xor_sync(0xffffffffu, oA, 2);
        oB += __shfl_xor_sync(0xffffffffu, oB, 1);
        oB += __shfl_xor_sync(0xffffffffu, oB, 2);
        if (tig == 0) {
            int row = wm * 64 + mt * 16 + gid;
            sRed[wn * 128 + row] = oA;
            sRed[wn * 128 + row + 8] = oB;
        }
    }
    __syncthreads();
    if (t < 128 && pt0 + t < nTot)
        out[pt0 + t] = sEx[4] + sRed[t] + sRed[128 + t]
                               + sRed[256 + t] + sRed[384 + t];
}

// ---------------------------------------------------------------------------
extern "C" void kernel_launch(void* const* d_in, const int* in_sizes, int n_in,
                              void* d_out, int out_size)
{
    const float* coords = (const float*)d_in[0];
    const float* W0 = (const float*)d_in[1];
    const float* W1 = (const float*)d_in[3];
    const float* W2 = (const float*)d_in[5];
    float* out = (float*)d_out;

    int n = in_sizes[0] / 3;
    prep_kernel<<<(N_UNITS + 255) / 256, 256>>>(W0, W1, W2);
    cudaFuncSetAttribute(mlp3d_main,
                         cudaFuncAttributeMaxDynamicSharedMemorySize,
                         SMEM_BYTES);
    mlp3d_main<<<(n + 127) / 128, 256, SMEM_BYTES>>>(
        coords, (const float*)d_in[2], (const float*)d_in[4],
        (const float*)d_in[6], (const float*)d_in[7], (const float*)d_in[8],
        (const float*)d_in[9], (const float*)d_in[10], out, n);
}

// round 9
// speedup vs baseline: 4.1193x; 1.2375x over previous
#include <cuda_runtime.h>
#include <cuda_fp16.h>
#include <math.h>

// ============================================================================
// MLP3D via fp16 mma.sync.m16n8k16, asymmetric split: A = fp16 (single),
// B = fp16 hi + lo (split at prep) => 2 products per logical MMA.
// Block = 128 points, 256 threads = 8 warps tiled 2(M)x4(N).
// B fragments pre-packed (uint4 = hi.k01,hi.k89,lo.k01,lo.k89), read directly
// from L2 via LDG.128 with one-k-tile register ping-pong prefetch.
// Output: out[0..n) = occ ; out[n..5n) = part_class [N,4] row-major.
// ============================================================================

#define LDA 264
#define CH_L0 0
#define CH_L1 4
#define CH_L2 20
#define CH_BD 36
#define N_UNITS (40 * 1024)

__device__ uint4 gW[N_UNITS];

#define SC_OFF (128 * LDA * 2)             // 67584 (sActH only, fp16)
#define SMEM_BYTES (SC_OFF + 1800 * 4)

typedef unsigned u32;

__device__ __forceinline__ u32 pack2h(__half a, __half b) {
    return (u32)__half_as_ushort(a) | ((u32)__half_as_ushort(b) << 16);
}
__device__ __forceinline__ void mma16816(float d[4], const u32 a[4],
                                         u32 b0, u32 b1) {
    asm volatile(
        "mma.sync.aligned.m16n8k16.row.col.f32.f16.f16.f32 "
        "{%0,%1,%2,%3},{%4,%5,%6,%7},{%8,%9},{%0,%1,%2,%3};"
        : "+f"(d[0]), "+f"(d[1]), "+f"(d[2]), "+f"(d[3])
        : "r"(a[0]), "r"(a[1]), "r"(a[2]), "r"(a[3]), "r"(b0), "r"(b1));
}
__device__ __forceinline__ void ldsm4(u32 r[4], const __half* p) {
    u32 a = (u32)__cvta_generic_to_shared(p);
    asm volatile("ldmatrix.sync.aligned.m8n8.x4.shared.b16 {%0,%1,%2,%3}, [%4];"
                 : "=r"(r[0]), "=r"(r[1]), "=r"(r[2]), "=r"(r[3]) : "r"(a));
}

// ---------------------------------------------------------------------------
__global__ void prep_kernel(const float* __restrict__ W0,
                            const float* __restrict__ W1,
                            const float* __restrict__ W2) {
    int idx = blockIdx.x * blockDim.x + threadIdx.x;
    if (idx >= N_UNITS) return;
    const float* W; int Kact, kt, tig, nn, rowOff = 0, colOff = 0;
    if (idx < 4096)        { W = W0; Kact = 63;
        kt = idx >> 10; int r = idx & 1023; tig = r >> 8; nn = r & 255; }
    else if (idx < 20480)  { W = W1; Kact = 256; int u = idx - 4096;
        kt = u >> 10; int r = u & 1023; tig = r >> 8; nn = r & 255; }
    else if (idx < 36864)  { W = W2; Kact = 256; int u = idx - 20480;
        kt = u >> 10; int r = u & 1023; tig = r >> 8; nn = r & 255; }
    else {                   W = W1; Kact = 64; int u = idx - 36864;
        int p = u >> 10; int r = u & 1023;
        kt = r >> 8; tig = (r >> 6) & 3; nn = r & 63;
        rowOff = 64 * p; colOff = 64 * p; }
    int k0 = 16 * kt + 2 * tig;
    int ks[4] = {k0, k0 + 1, k0 + 8, k0 + 9};
    __half h[4], l[4];
#pragma unroll
    for (int i = 0; i < 4; ++i) {
        float v = (ks[i] < Kact) ? W[(rowOff + ks[i]) * 256 + colOff + nn] : 0.f;
        h[i] = __float2half_rn(v);
        l[i] = __float2half_rn(v - __half2float(h[i]));
    }
    gW[idx] = make_uint4(pack2h(h[0], h[1]), pack2h(h[2], h[3]),
                         pack2h(l[0], l[1]), pack2h(l[2], l[3]));
}

// ---------------------------------------------------------------------------
// one k-tile: ldsm A, prefetch next B into bn, 64 MMAs on bc (dep distance 8)
__device__ __forceinline__ void kt_step(
    float (&acc)[4][8][4], const uint4* __restrict__ gB,
    uint4 (&bc)[8], uint4 (&bn)[8], int ktNext, int KT, int kt,
    const __half* aP)
{
    u32 ah[4][4];
#pragma unroll
    for (int mt = 0; mt < 4; ++mt)
        ldsm4(ah[mt], aP + mt * 16 * LDA + kt * 16);
    if (ktNext < KT) {
#pragma unroll
        for (int nt = 0; nt < 8; ++nt) bn[nt] = gB[ktNext * 1024 + nt * 8];
    }
#pragma unroll
    for (int np = 0; np < 4; ++np) {
        const int n0 = 2 * np, n1 = n0 + 1;
#pragma unroll
        for (int mt = 0; mt < 4; ++mt) mma16816(acc[mt][n0], ah[mt], bc[n0].x, bc[n0].y);
#pragma unroll
        for (int mt = 0; mt < 4; ++mt) mma16816(acc[mt][n1], ah[mt], bc[n1].x, bc[n1].y);
#pragma unroll
        for (int mt = 0; mt < 4; ++mt) mma16816(acc[mt][n0], ah[mt], bc[n0].z, bc[n0].w);
#pragma unroll
        for (int mt = 0; mt < 4; ++mt) mma16816(acc[mt][n1], ah[mt], bc[n1].z, bc[n1].w);
    }
}

template <int KT>
__device__ __forceinline__ void trunk_layer(
    float (&acc)[4][8][4], int chunkBase,
    const __half* aP, int tig, int gid, int wn)
{
#pragma unroll
    for (int mt = 0; mt < 4; ++mt)
#pragma unroll
        for (int nt = 0; nt < 8; ++nt)
            acc[mt][nt][0] = acc[mt][nt][1] = acc[mt][nt][2] = acc[mt][nt][3] = 0.f;

    const uint4* __restrict__ gB = gW + chunkBase * 1024 + tig * 256 + wn * 64 + gid;
    uint4 bc[8], bn[8];
#pragma unroll
    for (int nt = 0; nt < 8; ++nt) bc[nt] = gB[nt * 8];
#pragma unroll 1
    for (int kt = 0; kt < KT; kt += 2) {          // KT is even
        kt_step(acc, gB, bc, bn, kt + 1, KT, kt,     aP);
        kt_step(acc, gB, bn, bc, kt + 2, KT, kt + 1, aP);
    }
}

// ---------------------------------------------------------------------------
__global__ void __launch_bounds__(256, 1)
mlp3d_main(const float* __restrict__ coords,
           const float* __restrict__ b0g, const float* __restrict__ b1g,
           const float* __restrict__ b2g, const float* __restrict__ Woccg,
           const float* __restrict__ boccg, const float* __restrict__ Wcg,
           const float* __restrict__ bcg, float* __restrict__ out, int nTot)
{
    extern __shared__ char smem[];
    __half* sActH = (__half*)smem;
    float* sC = (float*)(smem + SC_OFF);
    float *sB0 = sC, *sB1 = sC + 256, *sB2 = sC + 512;
    float *sWocc = sC + 768, *sWcS = sC + 1024, *sEx = sC + 1280;
    float *sRed = sC + 1288;                      // 512 floats

    const int t = threadIdx.x, wid = t >> 5, lane = t & 31;
    const int tig = lane & 3, gid = lane >> 2;
    const int wm = wid & 1, wn = wid >> 1;
    const int pt0 = blockIdx.x * 128;

    sB0[t] = b0g[t]; sB1[t] = b1g[t]; sB2[t] = b2g[t]; sWocc[t] = Woccg[t];
    { int p = t >> 6, j = t & 63; sWcS[t] = Wcg[p * 256 + p * 64 + j]; }
    if (t < 4) sEx[t] = bcg[t];
    if (t == 4) sEx[4] = boccg[0];

    // ---- embedding (cols 0..62, col 63 zero) ----
    if (t < 128) sActH[t * LDA + 63] = __float2half(0.f);
    for (int idx = t; idx < 384; idx += 256) {
        int pt = idx / 3, d = idx % 3;
        float c = (pt0 + pt < nTot) ? coords[(pt0 + pt) * 3 + d] : 0.f;
        __half* rh = sActH + pt * LDA;
        rh[d] = __float2half_rn(c);
        float ang = c;
#pragma unroll
        for (int f = 0; f < 10; ++f) {
            float s, co; sincosf(ang, &s, &co);
            rh[3 + 6 * f + d] = __float2half_rn(s);
            rh[6 + 6 * f + d] = __float2half_rn(co);
            ang += ang;
        }
    }
    __syncthreads();

    const int lr = lane & 7, sel = lane >> 3;
    const int rowc = ((sel & 1) << 3) + lr, acol = (sel >> 1) << 3;
    const __half* aP  = sActH + (wm * 64 + rowc) * LDA + acol;
    const __half* aPp = sActH + (wid * 16 + rowc) * LDA + acol;

    float acc[4][8][4];

    // ======== L0: x = emb @ W0 + b0 (no relu) ========
    trunk_layer<4>(acc, CH_L0, aP, tig, gid, wn);
    __syncthreads();
#pragma unroll
    for (int mt = 0; mt < 4; ++mt) {
        int row = wm * 64 + mt * 16 + gid;
#pragma unroll
        for (int nt = 0; nt < 8; ++nt) {
            int n = (wn * 8 + nt) * 8 + 2 * tig;
            float ba = sB0[n], bb = sB0[n + 1];
            *(u32*)(sActH + row * LDA + n) =
                pack2h(__float2half_rn(acc[mt][nt][0] + ba),
                       __float2half_rn(acc[mt][nt][1] + bb));
            *(u32*)(sActH + (row + 8) * LDA + n) =
                pack2h(__float2half_rn(acc[mt][nt][2] + ba),
                       __float2half_rn(acc[mt][nt][3] + bb));
        }
    }
    __syncthreads();

    // ======== part branches (read x; direct-from-global B) ========
#pragma unroll 1
    for (int p = 0; p < 4; ++p) {
        const uint4* __restrict__ gBp =
            gW + (CH_BD + p) * 1024 + tig * 64 + gid;
        float pacc[8][4];
#pragma unroll
        for (int i = 0; i < 8; ++i)
            pacc[i][0] = pacc[i][1] = pacc[i][2] = pacc[i][3] = 0.f;
        uint4 pc[8], pn[8];
#pragma unroll
        for (int nt = 0; nt < 8; ++nt) pc[nt] = gBp[nt * 8];
#pragma unroll
        for (int kt = 0; kt < 4; ++kt) {
            u32 ah[4];
            ldsm4(ah, aPp + p * 64 + kt * 16);
            if (kt < 3) {
#pragma unroll
                for (int nt = 0; nt < 8; ++nt)
                    pn[nt] = gBp[(kt + 1) * 256 + nt * 8];
            }
#pragma unroll
            for (int np = 0; np < 4; ++np) {
                const int n0 = 2 * np, n1 = n0 + 1;
                mma16816(pacc[n0], ah, pc[n0].x, pc[n0].y);
                mma16816(pacc[n1], ah, pc[n1].x, pc[n1].y);
                mma16816(pacc[n0], ah, pc[n0].z, pc[n0].w);
                mma16816(pacc[n1], ah, pc[n1].z, pc[n1].w);
            }
#pragma unroll
            for (int nt = 0; nt < 8; ++nt) pc[nt] = pn[nt];
        }
        float sA = 0.f, sBv = 0.f;
#pragma unroll
        for (int nt = 0; nt < 8; ++nt) {
            int n = nt * 8 + 2 * tig;
            float ba = sB1[64 * p + n], bb2 = sB1[64 * p + n + 1];
            float wa = sWcS[64 * p + n], wb = sWcS[64 * p + n + 1];
            sA += fmaxf(pacc[nt][0] + ba, 0.f) * wa
                + fmaxf(pacc[nt][1] + bb2, 0.f) * wb;
            sBv += fmaxf(pacc[nt][2] + ba, 0.f) * wa
                 + fmaxf(pacc[nt][3] + bb2, 0.f) * wb;
        }
        sA += __shfl_xor_sync(0xffffffffu, sA, 1);
        sA += __shfl_xor_sync(0xffffffffu, sA, 2);
        sBv += __shfl_xor_sync(0xffffffffu, sBv, 1);
        sBv += __shfl_xor_sync(0xffffffffu, sBv, 2);
        if (tig == 0) {
            int m = wid * 16 + gid;
            if (pt0 + m < nTot)
                out[nTot + (pt0 + m) * 4 + p] = sA + sEx[p];
            if (pt0 + m + 8 < nTot)
                out[nTot + (pt0 + m + 8) * 4 + p] = sBv + sEx[p];
        }
    }

    // ======== L1: h = relu(x @ W1 + b1), in-place ========
    trunk_layer<16>(acc, CH_L1, aP, tig, gid, wn);
    __syncthreads();
#pragma unroll
    for (int mt = 0; mt < 4; ++mt) {
        int row = wm * 64 + mt * 16 + gid;
#pragma unroll
        for (int nt = 0; nt < 8; ++nt) {
            int n = (wn * 8 + nt) * 8 + 2 * tig;
            float ba = sB1[n], bb = sB1[n + 1];
            *(u32*)(sActH + row * LDA + n) =
                pack2h(__float2half_rn(fmaxf(acc[mt][nt][0] + ba, 0.f)),
                       __float2half_rn(fmaxf(acc[mt][nt][1] + bb, 0.f)));
            *(u32*)(sActH + (row + 8) * LDA + n) =
                pack2h(__float2half_rn(fmaxf(acc[mt][nt][2] + ba, 0.f)),
                       __float2half_rn(fmaxf(acc[mt][nt][3] + bb, 0.f)));
        }
    }
    __syncthreads();

    // ======== L2 + fused occ head (cross-warp reduction over wn) ========
    trunk_layer<16>(acc, CH_L2, aP, tig, gid, wn);
#pragma unroll
    for (int mt = 0; mt < 4; ++mt) {
        float oA = 0.f, oB = 0.f;
#pragma unroll
        for (int nt = 0; nt < 8; ++nt) {
            int n = (wn * 8 + nt) * 8 + 2 * tig;
            float ba = sB2[n], bb = sB2[n + 1];
            float wa = sWocc[n], wb = sWocc[n + 1];
            oA += fmaxf(acc[mt][nt][0] + ba, 0.f) * wa
                + fmaxf(acc[mt][nt][1] + bb, 0.f) * wb;
            oB += fmaxf(acc[mt][nt][2] + ba, 0.f) * wa
                + fmaxf(acc[mt][nt][3] + bb, 0.f) * wb;
        }
        oA += __shfl_xor_sync(0xffffffffu, oA, 1);
        oA += __shfl_xor_sync(0xffffffffu, oA, 2);
        oB += __shfl_xor_sync(0xffffffffu, oB, 1);
        oB += __shfl_xor_sync(0xffffffffu, oB, 2);
        if (tig == 0) {
            int row = wm * 64 + mt * 16 + gid;
            sRed[wn * 128 + row] = oA;
            sRed[wn * 128 + row + 8] = oB;
        }
    }
    __syncthreads();
    if (t < 128 && pt0 + t < nTot)
        out[pt0 + t] = sEx[4] + sRed[t] + sRed[128 + t]
                               + sRed[256 + t] + sRed[384 + t];
}

// ---------------------------------------------------------------------------
extern "C" void kernel_launch(void* const* d_in, const int* in_sizes, int n_in,
                              void* d_out, int out_size)
{
    const float* coords = (const float*)d_in[0];
    const float* W0 = (const float*)d_in[1];
    const float* W1 = (const float*)d_in[3];
    const float* W2 = (const float*)d_in[5];
    float* out = (float*)d_out;

    int n = in_sizes[0] / 3;
    prep_kernel<<<(N_UNITS + 255) / 256, 256>>>(W0, W1, W2);
    cudaFuncSetAttribute(mlp3d_main,
                         cudaFuncAttributeMaxDynamicSharedMemorySize,
                         SMEM_BYTES);
    mlp3d_main<<<(n + 127) / 128, 256, SMEM_BYTES>>>(
        coords, (const float*)d_in[2], (const float*)d_in[4],
        (const float*)d_in[6], (const float*)d_in[7], (const float*)d_in[8],
        (const float*)d_in[9], (const float*)d_in[10], out, n);
}

// round 10
// speedup vs baseline: 4.1891x; 1.0169x over previous
#include <cuda_runtime.h>
#include <cuda_fp16.h>
#include <math.h>

// ============================================================================
// MLP3D via fp16 mma.sync.m16n8k16, asymmetric split: A = fp16 (single),
// B = fp16 hi + lo (split at prep) => 2 products per logical MMA.
// Block = 128 points, 256 threads = 8 warps tiled 2(M)x4(N).
// B fragments pre-packed (uint4 = hi.k01,hi.k89,lo.k01,lo.k89), read directly
// from L2 via LDG.128; BOTH A (ldmatrix) and B (LDG) are double-buffered one
// k-tile ahead. MMA order: all-hi then all-lo => same-acc dep distance 32.
// Output: out[0..n) = occ ; out[n..5n) = part_class [N,4] row-major.
// ============================================================================

#define LDA 264
#define CH_L0 0
#define CH_L1 4
#define CH_L2 20
#define CH_BD 36
#define N_UNITS (40 * 1024)

__device__ uint4 gW[N_UNITS];

#define SC_OFF (128 * LDA * 2)             // 67584 (sActH only, fp16)
#define SMEM_BYTES (SC_OFF + 1800 * 4)

typedef unsigned u32;

__device__ __forceinline__ u32 pack2h(__half a, __half b) {
    return (u32)__half_as_ushort(a) | ((u32)__half_as_ushort(b) << 16);
}
__device__ __forceinline__ void mma16816(float d[4], const u32 a[4],
                                         u32 b0, u32 b1) {
    asm volatile(
        "mma.sync.aligned.m16n8k16.row.col.f32.f16.f16.f32 "
        "{%0,%1,%2,%3},{%4,%5,%6,%7},{%8,%9},{%0,%1,%2,%3};"
        : "+f"(d[0]), "+f"(d[1]), "+f"(d[2]), "+f"(d[3])
        : "r"(a[0]), "r"(a[1]), "r"(a[2]), "r"(a[3]), "r"(b0), "r"(b1));
}
__device__ __forceinline__ void ldsm4(u32 r[4], const __half* p) {
    u32 a = (u32)__cvta_generic_to_shared(p);
    asm volatile("ldmatrix.sync.aligned.m8n8.x4.shared.b16 {%0,%1,%2,%3}, [%4];"
                 : "=r"(r[0]), "=r"(r[1]), "=r"(r[2]), "=r"(r[3]) : "r"(a));
}

// ---------------------------------------------------------------------------
__global__ void prep_kernel(const float* __restrict__ W0,
                            const float* __restrict__ W1,
                            const float* __restrict__ W2) {
    int idx = blockIdx.x * blockDim.x + threadIdx.x;
    if (idx >= N_UNITS) return;
    const float* W; int Kact, kt, tig, nn, rowOff = 0, colOff = 0;
    if (idx < 4096)        { W = W0; Kact = 63;
        kt = idx >> 10; int r = idx & 1023; tig = r >> 8; nn = r & 255; }
    else if (idx < 20480)  { W = W1; Kact = 256; int u = idx - 4096;
        kt = u >> 10; int r = u & 1023; tig = r >> 8; nn = r & 255; }
    else if (idx < 36864)  { W = W2; Kact = 256; int u = idx - 20480;
        kt = u >> 10; int r = u & 1023; tig = r >> 8; nn = r & 255; }
    else {                   W = W1; Kact = 64; int u = idx - 36864;
        int p = u >> 10; int r = u & 1023;
        kt = r >> 8; tig = (r >> 6) & 3; nn = r & 63;
        rowOff = 64 * p; colOff = 64 * p; }
    int k0 = 16 * kt + 2 * tig;
    int ks[4] = {k0, k0 + 1, k0 + 8, k0 + 9};
    __half h[4], l[4];
#pragma unroll
    for (int i = 0; i < 4; ++i) {
        float v = (ks[i] < Kact) ? W[(rowOff + ks[i]) * 256 + colOff + nn] : 0.f;
        h[i] = __float2half_rn(v);
        l[i] = __float2half_rn(v - __half2float(h[i]));
    }
    gW[idx] = make_uint4(pack2h(h[0], h[1]), pack2h(h[2], h[3]),
                         pack2h(l[0], l[1]), pack2h(l[2], l[3]));
}

// ---------------------------------------------------------------------------
// 64 MMAs on one k-tile: all 32 hi products, then all 32 lo products.
// Same-accumulator reuse distance = 32.
__device__ __forceinline__ void mma_block(
    float (&acc)[4][8][4], const u32 (&a)[4][4], const uint4 (&b)[8])
{
#pragma unroll
    for (int nt = 0; nt < 8; ++nt)
#pragma unroll
        for (int mt = 0; mt < 4; ++mt)
            mma16816(acc[mt][nt], a[mt], b[nt].x, b[nt].y);
#pragma unroll
    for (int nt = 0; nt < 8; ++nt)
#pragma unroll
        for (int mt = 0; mt < 4; ++mt)
            mma16816(acc[mt][nt], a[mt], b[nt].z, b[nt].w);
}
__device__ __forceinline__ void lda4(u32 (&a)[4][4], const __half* aP, int kt) {
#pragma unroll
    for (int mt = 0; mt < 4; ++mt)
        ldsm4(a[mt], aP + mt * 16 * LDA + kt * 16);
}

template <int KT>
__device__ __forceinline__ void trunk_layer(
    float (&acc)[4][8][4], int chunkBase,
    const __half* aP, int tig, int gid, int wn)
{
#pragma unroll
    for (int mt = 0; mt < 4; ++mt)
#pragma unroll
        for (int nt = 0; nt < 8; ++nt)
            acc[mt][nt][0] = acc[mt][nt][1] = acc[mt][nt][2] = acc[mt][nt][3] = 0.f;

    const uint4* __restrict__ gB = gW + chunkBase * 1024 + tig * 256 + wn * 64 + gid;
    uint4 bc[8], bn[8];
    u32 a0[4][4], a1[4][4];
#pragma unroll
    for (int nt = 0; nt < 8; ++nt) bc[nt] = gB[nt * 8];
    lda4(a0, aP, 0);
#pragma unroll 1
    for (int kt = 0; kt < KT; kt += 2) {          // KT is even
        if (kt + 1 < KT) {
#pragma unroll
            for (int nt = 0; nt < 8; ++nt) bn[nt] = gB[(kt + 1) * 1024 + nt * 8];
            lda4(a1, aP, kt + 1);
        }
        mma_block(acc, a0, bc);
        if (kt + 2 < KT) {
#pragma unroll
            for (int nt = 0; nt < 8; ++nt) bc[nt] = gB[(kt + 2) * 1024 + nt * 8];
            lda4(a0, aP, kt + 2);
        }
        if (kt + 1 < KT) mma_block(acc, a1, bn);
    }
}

// ---------------------------------------------------------------------------
__global__ void __launch_bounds__(256, 1)
mlp3d_main(const float* __restrict__ coords,
           const float* __restrict__ b0g, const float* __restrict__ b1g,
           const float* __restrict__ b2g, const float* __restrict__ Woccg,
           const float* __restrict__ boccg, const float* __restrict__ Wcg,
           const float* __restrict__ bcg, float* __restrict__ out, int nTot)
{
    extern __shared__ char smem[];
    __half* sActH = (__half*)smem;
    float* sC = (float*)(smem + SC_OFF);
    float *sB0 = sC, *sB1 = sC + 256, *sB2 = sC + 512;
    float *sWocc = sC + 768, *sWcS = sC + 1024, *sEx = sC + 1280;
    float *sRed = sC + 1288;                      // 512 floats

    const int t = threadIdx.x, wid = t >> 5, lane = t & 31;
    const int tig = lane & 3, gid = lane >> 2;
    const int wm = wid & 1, wn = wid >> 1;
    const int pt0 = blockIdx.x * 128;

    sB0[t] = b0g[t]; sB1[t] = b1g[t]; sB2[t] = b2g[t]; sWocc[t] = Woccg[t];
    { int p = t >> 6, j = t & 63; sWcS[t] = Wcg[p * 256 + p * 64 + j]; }
    if (t < 4) sEx[t] = bcg[t];
    if (t == 4) sEx[4] = boccg[0];

    // ---- embedding (cols 0..62, col 63 zero) ----
    if (t < 128) sActH[t * LDA + 63] = __float2half(0.f);
    for (int idx = t; idx < 384; idx += 256) {
        int pt = idx / 3, d = idx % 3;
        float c = (pt0 + pt < nTot) ? coords[(pt0 + pt) * 3 + d] : 0.f;
        __half* rh = sActH + pt * LDA;
        rh[d] = __float2half_rn(c);
        float ang = c;
#pragma unroll
        for (int f = 0; f < 10; ++f) {
            float s, co; sincosf(ang, &s, &co);
            rh[3 + 6 * f + d] = __float2half_rn(s);
            rh[6 + 6 * f + d] = __float2half_rn(co);
            ang += ang;
        }
    }
    __syncthreads();

    const int lr = lane & 7, sel = lane >> 3;
    const int rowc = ((sel & 1) << 3) + lr, acol = (sel >> 1) << 3;
    const __half* aP  = sActH + (wm * 64 + rowc) * LDA + acol;
    const __half* aPp = sActH + (wid * 16 + rowc) * LDA + acol;

    float acc[4][8][4];

    // ======== L0: x = emb @ W0 + b0 (no relu) ========
    trunk_layer<4>(acc, CH_L0, aP, tig, gid, wn);
    __syncthreads();
#pragma unroll
    for (int mt = 0; mt < 4; ++mt) {
        int row = wm * 64 + mt * 16 + gid;
#pragma unroll
        for (int nt = 0; nt < 8; ++nt) {
            int n = (wn * 8 + nt) * 8 + 2 * tig;
            float ba = sB0[n], bb = sB0[n + 1];
            *(u32*)(sActH + row * LDA + n) =
                pack2h(__float2half_rn(acc[mt][nt][0] + ba),
                       __float2half_rn(acc[mt][nt][1] + bb));
            *(u32*)(sActH + (row + 8) * LDA + n) =
                pack2h(__float2half_rn(acc[mt][nt][2] + ba),
                       __float2half_rn(acc[mt][nt][3] + bb));
        }
    }
    __syncthreads();

    // ======== part branches (read x; direct-from-global B) ========
#pragma unroll 1
    for (int p = 0; p < 4; ++p) {
        const uint4* __restrict__ gBp =
            gW + (CH_BD + p) * 1024 + tig * 64 + gid;
        float pacc[8][4];
#pragma unroll
        for (int i = 0; i < 8; ++i)
            pacc[i][0] = pacc[i][1] = pacc[i][2] = pacc[i][3] = 0.f;
        uint4 pc[8], pn[8];
        u32 pa[2][4];
#pragma unroll
        for (int nt = 0; nt < 8; ++nt) pc[nt] = gBp[nt * 8];
        ldsm4(pa[0], aPp + p * 64);
#pragma unroll
        for (int kt = 0; kt < 4; ++kt) {
            if (kt < 3) {
#pragma unroll
                for (int nt = 0; nt < 8; ++nt)
                    pn[nt] = gBp[(kt + 1) * 256 + nt * 8];
                ldsm4(pa[(kt + 1) & 1], aPp + p * 64 + (kt + 1) * 16);
            }
#pragma unroll
            for (int nt = 0; nt < 8; ++nt)
                mma16816(pacc[nt], pa[kt & 1], pc[nt].x, pc[nt].y);
#pragma unroll
            for (int nt = 0; nt < 8; ++nt)
                mma16816(pacc[nt], pa[kt & 1], pc[nt].z, pc[nt].w);
            if (kt < 3) {
#pragma unroll
                for (int nt = 0; nt < 8; ++nt) pc[nt] = pn[nt];
            }
        }
        float sA = 0.f, sBv = 0.f;
#pragma unroll
        for (int nt = 0; nt < 8; ++nt) {
            int n = nt * 8 + 2 * tig;
            float ba = sB1[64 * p + n], bb2 = sB1[64 * p + n + 1];
            float wa = sWcS[64 * p + n], wb = sWcS[64 * p + n + 1];
            sA += fmaxf(pacc[nt][0] + ba, 0.f) * wa
                + fmaxf(pacc[nt][1] + bb2, 0.f) * wb;
            sBv += fmaxf(pacc[nt][2] + ba, 0.f) * wa
                 + fmaxf(pacc[nt][3] + bb2, 0.f) * wb;
        }
        sA += __shfl_xor_sync(0xffffffffu, sA, 1);
        sA += __shfl_xor_sync(0xffffffffu, sA, 2);
        sBv += __shfl_xor_sync(0xffffffffu, sBv, 1);
        sBv += __shfl_xor_sync(0xffffffffu, sBv, 2);
        if (tig == 0) {
            int m = wid * 16 + gid;
            if (pt0 + m < nTot)
                out[nTot + (pt0 + m) * 4 + p] = sA + sEx[p];
            if (pt0 + m + 8 < nTot)
                out[nTot + (pt0 + m + 8) * 4 + p] = sBv + sEx[p];
        }
    }

    // ======== L1: h = relu(x @ W1 + b1), in-place ========
    trunk_layer<16>(acc, CH_L1, aP, tig, gid, wn);
    __syncthreads();
#pragma unroll
    for (int mt = 0; mt < 4; ++mt) {
        int row = wm * 64 + mt * 16 + gid;
#pragma unroll
        for (int nt = 0; nt < 8; ++nt) {
            int n = (wn * 8 + nt) * 8 + 2 * tig;
            float ba = sB1[n], bb = sB1[n + 1];
            *(u32*)(sActH + row * LDA + n) =
                pack2h(__float2half_rn(fmaxf(acc[mt][nt][0] + ba, 0.f)),
                       __float2half_rn(fmaxf(acc[mt][nt][1] + bb, 0.f)));
            *(u32*)(sActH + (row + 8) * LDA + n) =
                pack2h(__float2half_rn(fmaxf(acc[mt][nt][2] + ba, 0.f)),
                       __float2half_rn(fmaxf(acc[mt][nt][3] + bb, 0.f)));
        }
    }
    __syncthreads();

    // ======== L2 + fused occ head (cross-warp reduction over wn) ========
    trunk_layer<16>(acc, CH_L2, aP, tig, gid, wn);
#pragma unroll
    for (int mt = 0; mt < 4; ++mt) {
        float oA = 0.f, oB = 0.f;
#pragma unroll
        for (int nt = 0; nt < 8; ++nt) {
            int n = (wn * 8 + nt) * 8 + 2 * tig;
            float ba = sB2[n], bb = sB2[n + 1];
            float wa = sWocc[n], wb = sWocc[n + 1];
            oA += fmaxf(acc[mt][nt][0] + ba, 0.f) * wa
                + fmaxf(acc[mt][nt][1] + bb, 0.f) * wb;
            oB += fmaxf(acc[mt][nt][2] + ba, 0.f) * wa
                + fmaxf(acc[mt][nt][3] + bb, 0.f) * wb;
        }
        oA += __shfl_xor_sync(0xffffffffu, oA, 1);
        oA += __shfl_xor_sync(0xffffffffu, oA, 2);
        oB += __shfl_xor_sync(0xffffffffu, oB, 1);
        oB += __shfl_xor_sync(0xffffffffu, oB, 2);
        if (tig == 0) {
            int row = wm * 64 + mt * 16 + gid;
            sRed[wn * 128 + row] = oA;
            sRed[wn * 128 + row + 8] = oB;
        }
    }
    __syncthreads();
    if (t < 128 && pt0 + t < nTot)
        out[pt0 + t] = sEx[4] + sRed[t] + sRed[128 + t]
                               + sRed[256 + t] + sRed[384 + t];
}

// ---------------------------------------------------------------------------
extern "C" void kernel_launch(void* const* d_in, const int* in_sizes, int n_in,
                              void* d_out, int out_size)
{
    const float* coords = (const float*)d_in[0];
    const float* W0 = (const float*)d_in[1];
    const float* W1 = (const float*)d_in[3];
    const float* W2 = (const float*)d_in[5];
    float* out = (float*)d_out;

    int n = in_sizes[0] / 3;
    prep_kernel<<<(N_UNITS + 255) / 256, 256>>>(W0, W1, W2);
    cudaFuncSetAttribute(mlp3d_main,
                         cudaFuncAttributeMaxDynamicSharedMemorySize,
                         SMEM_BYTES);
    mlp3d_main<<<(n + 127) / 128, 256, SMEM_BYTES>>>(
        coords, (const float*)d_in[2], (const float*)d_in[4],
        (const float*)d_in[6], (const float*)d_in[7], (const float*)d_in[8],
        (const float*)d_in[9], (const float*)d_in[10], out, n);
}

// round 11
// speedup vs baseline: 6.1733x; 1.4737x over previous
#include <cuda_runtime.h>
#include <cuda_fp16.h>
#include <math.h>

// ============================================================================
// MLP3D via fp16 mma.sync.m16n8k16.
// L0: A fp16, B fp16 hi+lo (2 products)  — protects the embedding layer.
// L1/L2/parts: plain fp16 B (1 product)  — halves MMAs and B bytes.
// Block = 128 points, 256 threads = 8 warps tiled 2(M)x4(N).
// B fragments pre-packed; read directly from L2 via LDG with one-k-tile
// register ping-pong prefetch (A via ldmatrix double-buffer).
// Output: out[0..n) = occ ; out[n..5n) = part_class [N,4] row-major.
// ============================================================================

#define LDA 264
#define U_L1 0
#define U_L2 16384
#define U_PT 32768

__device__ uint4 gW4[4096];      // L0: hi.k01,hi.k89,lo.k01,lo.k89
__device__ uint2 gW2[36864];     // L1/L2/parts: hi only

#define SC_OFF (128 * LDA * 2)             // 67584 (sActH only, fp16)
#define SMEM_BYTES (SC_OFF + 1800 * 4)

typedef unsigned u32;

__device__ __forceinline__ u32 pack2h(__half a, __half b) {
    return (u32)__half_as_ushort(a) | ((u32)__half_as_ushort(b) << 16);
}
__device__ __forceinline__ void mma16816(float d[4], const u32 a[4],
                                         u32 b0, u32 b1) {
    asm volatile(
        "mma.sync.aligned.m16n8k16.row.col.f32.f16.f16.f32 "
        "{%0,%1,%2,%3},{%4,%5,%6,%7},{%8,%9},{%0,%1,%2,%3};"
        : "+f"(d[0]), "+f"(d[1]), "+f"(d[2]), "+f"(d[3])
        : "r"(a[0]), "r"(a[1]), "r"(a[2]), "r"(a[3]), "r"(b0), "r"(b1));
}
__device__ __forceinline__ void ldsm4(u32 r[4], const __half* p) {
    u32 a = (u32)__cvta_generic_to_shared(p);
    asm volatile("ldmatrix.sync.aligned.m8n8.x4.shared.b16 {%0,%1,%2,%3}, [%4];"
                 : "=r"(r[0]), "=r"(r[1]), "=r"(r[2]), "=r"(r[3]) : "r"(a));
}
__device__ __forceinline__ void lda4(u32 (&a)[4][4], const __half* aP, int kt) {
#pragma unroll
    for (int mt = 0; mt < 4; ++mt)
        ldsm4(a[mt], aP + mt * 16 * LDA + kt * 16);
}

// ---------------------------------------------------------------------------
__global__ void prep_kernel(const float* __restrict__ W0,
                            const float* __restrict__ W1,
                            const float* __restrict__ W2) {
    int idx = blockIdx.x * blockDim.x + threadIdx.x;
    if (idx >= 40960) return;

    if (idx < 4096) {                        // L0: hi+lo uint4, Kact=63
        int kt = idx >> 10, r = idx & 1023, tig = r >> 8, nn = r & 255;
        int k0 = 16 * kt + 2 * tig;
        int ks[4] = {k0, k0 + 1, k0 + 8, k0 + 9};
        __half h[4], l[4];
#pragma unroll
        for (int i = 0; i < 4; ++i) {
            float v = (ks[i] < 63) ? W0[ks[i] * 256 + nn] : 0.f;
            h[i] = __float2half_rn(v);
            l[i] = __float2half_rn(v - __half2float(h[i]));
        }
        gW4[idx] = make_uint4(pack2h(h[0], h[1]), pack2h(h[2], h[3]),
                              pack2h(l[0], l[1]), pack2h(l[2], l[3]));
        return;
    }
    int u = idx - 4096;
    const float* W; int kt, tig, nn, rowOff = 0, colOff = 0;
    if (u < 16384)       { W = W1;
        kt = u >> 10; int r = u & 1023; tig = r >> 8; nn = r & 255; }
    else if (u < 32768)  { W = W2; int v = u - 16384;
        kt = v >> 10; int r = v & 1023; tig = r >> 8; nn = r & 255; }
    else {                 W = W1; int v = u - 32768;
        int p = v >> 10; int r = v & 1023;
        kt = r >> 8; tig = (r >> 6) & 3; nn = r & 63;
        rowOff = 64 * p; colOff = 64 * p; }
    int k0 = 16 * kt + 2 * tig;
    int ks[4] = {k0, k0 + 1, k0 + 8, k0 + 9};
    __half h[4];
#pragma unroll
    for (int i = 0; i < 4; ++i)
        h[i] = __float2half_rn(W[(rowOff + ks[i]) * 256 + colOff + nn]);
    gW2[u] = make_uint2(pack2h(h[0], h[1]), pack2h(h[2], h[3]));
}

// ---------------------------------------------------------------------------
// L0: 2-product (hi then lo), KT=4, B = gW4.
__device__ __forceinline__ void mma_block2(
    float (&acc)[4][8][4], const u32 (&a)[4][4], const uint4 (&b)[8])
{
#pragma unroll
    for (int nt = 0; nt < 8; ++nt)
#pragma unroll
        for (int mt = 0; mt < 4; ++mt)
            mma16816(acc[mt][nt], a[mt], b[nt].x, b[nt].y);
#pragma unroll
    for (int nt = 0; nt < 8; ++nt)
#pragma unroll
        for (int mt = 0; mt < 4; ++mt)
            mma16816(acc[mt][nt], a[mt], b[nt].z, b[nt].w);
}
__device__ __forceinline__ void trunk_L0(
    float (&acc)[4][8][4], const __half* aP, int tig, int gid, int wn)
{
#pragma unroll
    for (int mt = 0; mt < 4; ++mt)
#pragma unroll
        for (int nt = 0; nt < 8; ++nt)
            acc[mt][nt][0] = acc[mt][nt][1] = acc[mt][nt][2] = acc[mt][nt][3] = 0.f;
    const uint4* __restrict__ gB = gW4 + tig * 256 + wn * 64 + gid;
    uint4 bc[8], bn[8];
    u32 a0[4][4], a1[4][4];
#pragma unroll
    for (int nt = 0; nt < 8; ++nt) bc[nt] = gB[nt * 8];
    lda4(a0, aP, 0);
#pragma unroll 1
    for (int kt = 0; kt < 4; kt += 2) {
#pragma unroll
        for (int nt = 0; nt < 8; ++nt) bn[nt] = gB[(kt + 1) * 1024 + nt * 8];
        lda4(a1, aP, kt + 1);
        mma_block2(acc, a0, bc);
        if (kt + 2 < 4) {
#pragma unroll
            for (int nt = 0; nt < 8; ++nt) bc[nt] = gB[(kt + 2) * 1024 + nt * 8];
            lda4(a0, aP, kt + 2);
        }
        mma_block2(acc, a1, bn);
    }
}

// 1-product trunk layer (L1/L2), B = gW2 + ubase.
__device__ __forceinline__ void mma_block1(
    float (&acc)[4][8][4], const u32 (&a)[4][4], const uint2 (&b)[8])
{
#pragma unroll
    for (int nt = 0; nt < 8; ++nt)
#pragma unroll
        for (int mt = 0; mt < 4; ++mt)
            mma16816(acc[mt][nt], a[mt], b[nt].x, b[nt].y);
}
__device__ __forceinline__ void trunk_1p(
    float (&acc)[4][8][4], int ubase, const __half* aP,
    int tig, int gid, int wn)
{
#pragma unroll
    for (int mt = 0; mt < 4; ++mt)
#pragma unroll
        for (int nt = 0; nt < 8; ++nt)
            acc[mt][nt][0] = acc[mt][nt][1] = acc[mt][nt][2] = acc[mt][nt][3] = 0.f;
    const uint2* __restrict__ gB = gW2 + ubase + tig * 256 + wn * 64 + gid;
    uint2 bc[8], bn[8];
    u32 a0[4][4], a1[4][4];
#pragma unroll
    for (int nt = 0; nt < 8; ++nt) bc[nt] = gB[nt * 8];
    lda4(a0, aP, 0);
#pragma unroll 1
    for (int kt = 0; kt < 16; kt += 2) {
#pragma unroll
        for (int nt = 0; nt < 8; ++nt) bn[nt] = gB[(kt + 1) * 1024 + nt * 8];
        lda4(a1, aP, kt + 1);
        mma_block1(acc, a0, bc);
        if (kt + 2 < 16) {
#pragma unroll
            for (int nt = 0; nt < 8; ++nt) bc[nt] = gB[(kt + 2) * 1024 + nt * 8];
            lda4(a0, aP, kt + 2);
        }
        mma_block1(acc, a1, bn);
    }
}

// ---------------------------------------------------------------------------
__global__ void __launch_bounds__(256, 1)
mlp3d_main(const float* __restrict__ coords,
           const float* __restrict__ b0g, const float* __restrict__ b1g,
           const float* __restrict__ b2g, const float* __restrict__ Woccg,
           const float* __restrict__ boccg, const float* __restrict__ Wcg,
           const float* __restrict__ bcg, float* __restrict__ out, int nTot)
{
    extern __shared__ char smem[];
    __half* sActH = (__half*)smem;
    float* sC = (float*)(smem + SC_OFF);
    float *sB0 = sC, *sB1 = sC + 256, *sB2 = sC + 512;
    float *sWocc = sC + 768, *sWcS = sC + 1024, *sEx = sC + 1280;
    float *sRed = sC + 1288;                      // 512 floats

    const int t = threadIdx.x, wid = t >> 5, lane = t & 31;
    const int tig = lane & 3, gid = lane >> 2;
    const int wm = wid & 1, wn = wid >> 1;
    const int pt0 = blockIdx.x * 128;

    sB0[t] = b0g[t]; sB1[t] = b1g[t]; sB2[t] = b2g[t]; sWocc[t] = Woccg[t];
    { int p = t >> 6, j = t & 63; sWcS[t] = Wcg[p * 256 + p * 64 + j]; }
    if (t < 4) sEx[t] = bcg[t];
    if (t == 4) sEx[4] = boccg[0];

    // ---- embedding (cols 0..62, col 63 zero) ----
    if (t < 128) sActH[t * LDA + 63] = __float2half(0.f);
    for (int idx = t; idx < 384; idx += 256) {
        int pt = idx / 3, d = idx % 3;
        float c = (pt0 + pt < nTot) ? coords[(pt0 + pt) * 3 + d] : 0.f;
        __half* rh = sActH + pt * LDA;
        rh[d] = __float2half_rn(c);
        float ang = c;
#pragma unroll
        for (int f = 0; f < 10; ++f) {
            float s, co; sincosf(ang, &s, &co);
            rh[3 + 6 * f + d] = __float2half_rn(s);
            rh[6 + 6 * f + d] = __float2half_rn(co);
            ang += ang;
        }
    }
    __syncthreads();

    const int lr = lane & 7, sel = lane >> 3;
    const int rowc = ((sel & 1) << 3) + lr, acol = (sel >> 1) << 3;
    const __half* aP  = sActH + (wm * 64 + rowc) * LDA + acol;
    const __half* aPp = sActH + (wid * 16 + rowc) * LDA + acol;

    float acc[4][8][4];

    // ======== L0: x = emb @ W0 + b0 (no relu, 2-product) ========
    trunk_L0(acc, aP, tig, gid, wn);
    __syncthreads();
#pragma unroll
    for (int mt = 0; mt < 4; ++mt) {
        int row = wm * 64 + mt * 16 + gid;
#pragma unroll
        for (int nt = 0; nt < 8; ++nt) {
            int n = (wn * 8 + nt) * 8 + 2 * tig;
            float ba = sB0[n], bb = sB0[n + 1];
            *(u32*)(sActH + row * LDA + n) =
                pack2h(__float2half_rn(acc[mt][nt][0] + ba),
                       __float2half_rn(acc[mt][nt][1] + bb));
            *(u32*)(sActH + (row + 8) * LDA + n) =
                pack2h(__float2half_rn(acc[mt][nt][2] + ba),
                       __float2half_rn(acc[mt][nt][3] + bb));
        }
    }
    __syncthreads();

    // ======== part branches (1-product, B from gW2) ========
#pragma unroll 1
    for (int p = 0; p < 4; ++p) {
        const uint2* __restrict__ gBp =
            gW2 + U_PT + p * 1024 + tig * 64 + gid;
        float pacc[8][4];
#pragma unroll
        for (int i = 0; i < 8; ++i)
            pacc[i][0] = pacc[i][1] = pacc[i][2] = pacc[i][3] = 0.f;
        uint2 pc[8], pn[8];
        u32 pa[2][4];
#pragma unroll
        for (int nt = 0; nt < 8; ++nt) pc[nt] = gBp[nt * 8];
        ldsm4(pa[0], aPp + p * 64);
#pragma unroll
        for (int kt = 0; kt < 4; ++kt) {
            if (kt < 3) {
#pragma unroll
                for (int nt = 0; nt < 8; ++nt)
                    pn[nt] = gBp[(kt + 1) * 256 + nt * 8];
                ldsm4(pa[(kt + 1) & 1], aPp + p * 64 + (kt + 1) * 16);
            }
#pragma unroll
            for (int nt = 0; nt < 8; ++nt)
                mma16816(pacc[nt], pa[kt & 1], pc[nt].x, pc[nt].y);
            if (kt < 3) {
#pragma unroll
                for (int nt = 0; nt < 8; ++nt) pc[nt] = pn[nt];
            }
        }
        float sA = 0.f, sBv = 0.f;
#pragma unroll
        for (int nt = 0; nt < 8; ++nt) {
            int n = nt * 8 + 2 * tig;
            float ba = sB1[64 * p + n], bb2 = sB1[64 * p + n + 1];
            float wa = sWcS[64 * p + n], wb = sWcS[64 * p + n + 1];
            sA += fmaxf(pacc[nt][0] + ba, 0.f) * wa
                + fmaxf(pacc[nt][1] + bb2, 0.f) * wb;
            sBv += fmaxf(pacc[nt][2] + ba, 0.f) * wa
                 + fmaxf(pacc[nt][3] + bb2, 0.f) * wb;
        }
        sA += __shfl_xor_sync(0xffffffffu, sA, 1);
        sA += __shfl_xor_sync(0xffffffffu, sA, 2);
        sBv += __shfl_xor_sync(0xffffffffu, sBv, 1);
        sBv += __shfl_xor_sync(0xffffffffu, sBv, 2);
        if (tig == 0) {
            int m = wid * 16 + gid;
            if (pt0 + m < nTot)
                out[nTot + (pt0 + m) * 4 + p] = sA + sEx[p];
            if (pt0 + m + 8 < nTot)
                out[nTot + (pt0 + m + 8) * 4 + p] = sBv + sEx[p];
        }
    }

    // ======== L1: h = relu(x @ W1 + b1), in-place (1-product) ========
    trunk_1p(acc, U_L1, aP, tig, gid, wn);
    __syncthreads();
#pragma unroll
    for (int mt = 0; mt < 4; ++mt) {
        int row = wm * 64 + mt * 16 + gid;
#pragma unroll
        for (int nt = 0; nt < 8; ++nt) {
            int n = (wn * 8 + nt) * 8 + 2 * tig;
            float ba = sB1[n], bb = sB1[n + 1];
            *(u32*)(sActH + row * LDA + n) =
                pack2h(__float2half_rn(fmaxf(acc[mt][nt][0] + ba, 0.f)),
                       __float2half_rn(fmaxf(acc[mt][nt][1] + bb, 0.f)));
            *(u32*)(sActH + (row + 8) * LDA + n) =
                pack2h(__float2half_rn(fmaxf(acc[mt][nt][2] + ba, 0.f)),
                       __float2half_rn(fmaxf(acc[mt][nt][3] + bb, 0.f)));
        }
    }
    __syncthreads();

    // ======== L2 + fused occ head (1-product) ========
    trunk_1p(acc, U_L2, aP, tig, gid, wn);
#pragma unroll
    for (int mt = 0; mt < 4; ++mt) {
        float oA = 0.f, oB = 0.f;
#pragma unroll
        for (int nt = 0; nt < 8; ++nt) {
            int n = (wn * 8 + nt) * 8 + 2 * tig;
            float ba = sB2[n], bb = sB2[n + 1];
            float wa = sWocc[n], wb = sWocc[n + 1];
            oA += fmaxf(acc[mt][nt][0] + ba, 0.f) * wa
                + fmaxf(acc[mt][nt][1] + bb, 0.f) * wb;
            oB += fmaxf(acc[mt][nt][2] + ba, 0.f) * wa
                + fmaxf(acc[mt][nt][3] + bb, 0.f) * wb;
        }
        oA += __shfl_xor_sync(0xffffffffu, oA, 1);
        oA += __shfl_xor_sync(0xffffffffu, oA, 2);
        oB += __shfl_xor_sync(0xffffffffu, oB, 1);
        oB += __shfl_xor_sync(0xffffffffu, oB, 2);
        if (tig == 0) {
            int row = wm * 64 + mt * 16 + gid;
            sRed[wn * 128 + row] = oA;
            sRed[wn * 128 + row + 8] = oB;
        }
    }
    __syncthreads();
    if (t < 128 && pt0 + t < nTot)
        out[pt0 + t] = sEx[4] + sRed[t] + sRed[128 + t]
                               + sRed[256 + t] + sRed[384 + t];
}

// ---------------------------------------------------------------------------
extern "C" void kernel_launch(void* const* d_in, const int* in_sizes, int n_in,
                              void* d_out, int out_size)
{
    const float* coords = (const float*)d_in[0];
    const float* W0 = (const float*)d_in[1];
    const float* W1 = (const float*)d_in[3];
    const float* W2 = (const float*)d_in[5];
    float* out = (float*)d_out;

    int n = in_sizes[0] / 3;
    prep_kernel<<<160, 256>>>(W0, W1, W2);
    cudaFuncSetAttribute(mlp3d_main,
                         cudaFuncAttributeMaxDynamicSharedMemorySize,
                         SMEM_BYTES);
    mlp3d_main<<<(n + 127) / 128, 256, SMEM_BYTES>>>(
        coords, (const float*)d_in[2], (const float*)d_in[4],
        (const float*)d_in[6], (const float*)d_in[7], (const float*)d_in[8],
        (const float*)d_in[9], (const float*)d_in[10], out, n);
}